// round 13
// baseline (speedup 1.0000x reference)
#include <cuda_runtime.h>
#include <cuda_bf16.h>
#include <cuda_fp16.h>
#include <cstddef>
#include <cstdint>

#define BB   1024
#define TT   32
#define VV   1024
#define EE   512
#define HH   1024
#define OO   1024

// ---------------- device scratch (no runtime allocation) -------------------
__device__ float g_bfused[HH];
__device__ __half g_xproj[TT * BB * HH];     // fp16, bias folded in
__device__ __half g_msg_h[BB * TT * VV];
__device__ __nv_bfloat16 g_wembT_hi[VV * EE];
__device__ __nv_bfloat16 g_wembT_lo[VV * EE];
__device__ __nv_bfloat16 g_wih_hi[HH * EE];
__device__ __nv_bfloat16 g_wih_lo[HH * EE];
__device__ __half g_wf[HH * VV];             // W_fused, single fp16
__device__ __half g_whh[HH * HH];            // W_hh, single fp16
__device__ __half g_wout[OO * HH];           // W_out, single fp16
__device__ __half g_h[2][BB * HH];           // hidden state, single fp16
// per-bm-group barriers: [gid][0]=arrive count, [gid][1]=generation
// generation is monotonic across graph replays (targets are gen0-relative)
__device__ unsigned g_barg[8][2];

// ---------------- helpers ---------------------------------------------------
__device__ __forceinline__ void bf16_split(float x, __nv_bfloat16& h, __nv_bfloat16& l) {
    h = __float2bfloat16(x);
    l = __float2bfloat16(x - __bfloat162float(h));
}

__device__ __forceinline__ void ldsm_x4(uint32_t* r, uint32_t addr) {
    asm volatile("ldmatrix.sync.aligned.m8n8.x4.shared.b16 {%0,%1,%2,%3}, [%4];"
                 : "=r"(r[0]), "=r"(r[1]), "=r"(r[2]), "=r"(r[3]) : "r"(addr));
}

__device__ __forceinline__ void mma_bf16(float* d, const uint32_t* a, const uint32_t* b) {
    asm volatile("mma.sync.aligned.m16n8k16.row.col.f32.bf16.bf16.f32 "
                 "{%0,%1,%2,%3}, {%4,%5,%6,%7}, {%8,%9}, {%0,%1,%2,%3};"
                 : "+f"(d[0]), "+f"(d[1]), "+f"(d[2]), "+f"(d[3])
                 : "r"(a[0]), "r"(a[1]), "r"(a[2]), "r"(a[3]),
                   "r"(b[0]), "r"(b[1]));
}

__device__ __forceinline__ void mma_f16(float* d, const uint32_t* a, const uint32_t* b) {
    asm volatile("mma.sync.aligned.m16n8k16.row.col.f32.f16.f16.f32 "
                 "{%0,%1,%2,%3}, {%4,%5,%6,%7}, {%8,%9}, {%0,%1,%2,%3};"
                 : "+f"(d[0]), "+f"(d[1]), "+f"(d[2]), "+f"(d[3])
                 : "r"(a[0]), "r"(a[1]), "r"(a[2]), "r"(a[3]),
                   "r"(b[0]), "r"(b[1]));
}

__device__ __forceinline__ void cp16(uint32_t dst, const void* src) {
    asm volatile("cp.async.cg.shared.global [%0], [%1], 16;" :: "r"(dst), "l"(src));
}
#define CP_COMMIT() asm volatile("cp.async.commit_group;" ::: "memory")
#define CP_WAIT(n)  asm volatile("cp.async.wait_group %0;" :: "n"(n) : "memory")

// ---------------- tiling constants ------------------------------------------
constexpr int BM = 128, BN = 64, BK = 32, LDT = BK + 8, STAGES = 3;
constexpr int A_ELE = BM * LDT;                 // 5120
constexpr int B_ELE = BN * LDT;                 // 2560
constexpr int BF3_STG = 2 * A_ELE + 2 * B_ELE;
constexpr int BF3_SMEM = STAGES * BF3_STG * 2;
#define OFF_AHI 0
#define OFF_ALO (A_ELE)
#define OFF_BHI (2 * A_ELE)
#define OFF_BLO (2 * A_ELE + B_ELE)

// ---------------------------------------------------------------------------
// bf16 3-term GEMM (only for W_fused = W_ih @ W_emb, output single fp16)
// ---------------------------------------------------------------------------
__global__ __launch_bounds__(256)
void mma_gemm_bf3(const __nv_bfloat16* __restrict__ Ahi,
                  const __nv_bfloat16* __restrict__ Alo,
                  const __nv_bfloat16* __restrict__ Bhi,
                  const __nv_bfloat16* __restrict__ Blo,
                  __half* __restrict__ Cout,
                  int M, int N, int K) {
    extern __shared__ __align__(16) __nv_bfloat16 smem[];
    const uint32_t sb = (uint32_t)__cvta_generic_to_shared(smem);
    const int tid = threadIdx.x, lane = tid & 31, wid = tid >> 5;
    const int bm = blockIdx.y * BM, bn = blockIdx.x * BN;
    const int wm = (wid >> 2) * 64, wn = (wid & 3) * 16;
    const int CH = K / BK;

    const int a_r0 = tid >> 2, a_c = (tid & 3) * 8;
    const int a_r1 = (tid + 256) >> 2;
    const int b_r = tid >> 2;

    auto load_chunk = [&](int k0, int s) {
        const uint32_t st = sb + (uint32_t)(s * BF3_STG) * 2;
        const size_t ga0 = (size_t)(bm + a_r0) * K + k0 + a_c;
        const size_t ga1 = (size_t)(bm + a_r1) * K + k0 + a_c;
        const size_t gb  = (size_t)(bn + b_r ) * K + k0 + a_c;
        const uint32_t d0 = (uint32_t)(a_r0 * LDT + a_c) * 2;
        const uint32_t d1 = (uint32_t)(a_r1 * LDT + a_c) * 2;
        const uint32_t db = (uint32_t)(b_r  * LDT + a_c) * 2;
        cp16(st + OFF_AHI * 2 + d0, Ahi + ga0);
        cp16(st + OFF_AHI * 2 + d1, Ahi + ga1);
        cp16(st + OFF_ALO * 2 + d0, Alo + ga0);
        cp16(st + OFF_ALO * 2 + d1, Alo + ga1);
        cp16(st + OFF_BHI * 2 + db, Bhi + gb);
        cp16(st + OFF_BLO * 2 + db, Blo + gb);
    };

    const int a_row = wm + (lane & 7) + ((lane >> 3) & 1) * 8;
    const int a_col = (lane >> 4) * 8;
    const int b_row = wn + (lane >> 4) * 8 + (lane & 7);
    const int b_col = ((lane >> 3) & 1) * 8;
    const uint32_t aoff = (uint32_t)(a_row * LDT + a_col) * 2;
    const uint32_t boff = (uint32_t)(b_row * LDT + b_col) * 2;

    float acc[4][2][4] = {};

    #pragma unroll
    for (int s = 0; s < STAGES - 1; s++) { load_chunk(s * BK, s); CP_COMMIT(); }

    for (int c = 0; c < CH; c++) {
        CP_WAIT(STAGES - 2);
        __syncthreads();
        const int pc = c + STAGES - 1;
        if (pc < CH) load_chunk(pc * BK, pc % STAGES);
        CP_COMMIT();

        const uint32_t st = sb + (uint32_t)((c % STAGES) * BF3_STG) * 2;
        #pragma unroll
        for (int kk = 0; kk < BK; kk += 16) {
            uint32_t ah[4][4], al[4][4], bh[4], bl[4];
            #pragma unroll
            for (int i = 0; i < 4; i++) {
                ldsm_x4(ah[i], st + OFF_AHI * 2 + aoff + (uint32_t)(i * 16 * LDT + kk) * 2);
                ldsm_x4(al[i], st + OFF_ALO * 2 + aoff + (uint32_t)(i * 16 * LDT + kk) * 2);
            }
            ldsm_x4(bh, st + OFF_BHI * 2 + boff + (uint32_t)kk * 2);
            ldsm_x4(bl, st + OFF_BLO * 2 + boff + (uint32_t)kk * 2);
            #pragma unroll
            for (int i = 0; i < 4; i++)
                #pragma unroll
                for (int j = 0; j < 2; j++) {
                    mma_bf16(acc[i][j], ah[i], &bh[j * 2]);
                    mma_bf16(acc[i][j], ah[i], &bl[j * 2]);
                    mma_bf16(acc[i][j], al[i], &bh[j * 2]);
                }
        }
    }

    const int crow = lane >> 2, ccol = (lane & 3) * 2;
    #pragma unroll
    for (int i = 0; i < 4; i++)
        #pragma unroll
        for (int j = 0; j < 2; j++)
            #pragma unroll
            for (int half = 0; half < 2; half++) {
                const int m = bm + wm + i * 16 + crow + half * 8;
                const int n = bn + wn + j * 8 + ccol;
                __half2 hp = { __float2half_rn(acc[i][j][half * 2 + 0]),
                               __float2half_rn(acc[i][j][half * 2 + 1]) };
                *reinterpret_cast<__half2*>(&Cout[(size_t)m * N + n]) = hp;
            }
}

// ---------------------------------------------------------------------------
// fp16 GEMM (padded layout), 1 B plane:
//   OUT 0: fp32 out, no scatter          (out = h @ W_out^T + b_out)
//   OUT 1: fp16 out, scatter m -> (m%TT)*BB + m/TT   (x_proj)
// ---------------------------------------------------------------------------
template <int OUT>
__global__ __launch_bounds__(256)
void mma_gemm_h(const __half* __restrict__ A,
                const __half* __restrict__ Bhi,
                const float* __restrict__ bias,
                float* __restrict__ Cf,
                __half* __restrict__ Ch,
                int M, int N, int K) {
    constexpr int STG = A_ELE + B_ELE;
    extern __shared__ __align__(16) __half hsmem[];
    const uint32_t sb = (uint32_t)__cvta_generic_to_shared(hsmem);
    const int tid = threadIdx.x, lane = tid & 31, wid = tid >> 5;
    const int bm = blockIdx.y * BM, bn = blockIdx.x * BN;
    const int wm = (wid >> 2) * 64, wn = (wid & 3) * 16;
    const int CH = K / BK;

    const int a_r0 = tid >> 2, a_c = (tid & 3) * 8;
    const int a_r1 = (tid + 256) >> 2;
    const int b_r = tid >> 2;

    auto load_chunk = [&](int k0, int s) {
        const uint32_t st = sb + (uint32_t)(s * STG) * 2;
        const size_t ga0 = (size_t)(bm + a_r0) * K + k0 + a_c;
        const size_t ga1 = (size_t)(bm + a_r1) * K + k0 + a_c;
        const size_t gb  = (size_t)(bn + b_r ) * K + k0 + a_c;
        const uint32_t d0 = (uint32_t)(a_r0 * LDT + a_c) * 2;
        const uint32_t d1 = (uint32_t)(a_r1 * LDT + a_c) * 2;
        const uint32_t db = (uint32_t)(b_r  * LDT + a_c) * 2;
        cp16(st + d0, A + ga0);
        cp16(st + d1, A + ga1);
        cp16(st + (uint32_t)A_ELE * 2 + db, Bhi + gb);
    };

    const int a_row = wm + (lane & 7) + ((lane >> 3) & 1) * 8;
    const int a_col = (lane >> 4) * 8;
    const int b_row = wn + (lane >> 4) * 8 + (lane & 7);
    const int b_col = ((lane >> 3) & 1) * 8;
    const uint32_t aoff = (uint32_t)(a_row * LDT + a_col) * 2;
    const uint32_t boff = (uint32_t)(b_row * LDT + b_col) * 2;

    float acc[4][2][4] = {};

    #pragma unroll
    for (int s = 0; s < STAGES - 1; s++) { load_chunk(s * BK, s); CP_COMMIT(); }

    for (int c = 0; c < CH; c++) {
        CP_WAIT(STAGES - 2);
        __syncthreads();
        const int pc = c + STAGES - 1;
        if (pc < CH) load_chunk(pc * BK, pc % STAGES);
        CP_COMMIT();

        const uint32_t st = sb + (uint32_t)((c % STAGES) * STG) * 2;
        #pragma unroll
        for (int kk = 0; kk < BK; kk += 16) {
            uint32_t a4[4][4], bh[4];
            #pragma unroll
            for (int i = 0; i < 4; i++)
                ldsm_x4(a4[i], st + aoff + (uint32_t)(i * 16 * LDT + kk) * 2);
            ldsm_x4(bh, st + (uint32_t)A_ELE * 2 + boff + (uint32_t)kk * 2);
            #pragma unroll
            for (int i = 0; i < 4; i++)
                #pragma unroll
                for (int j = 0; j < 2; j++)
                    mma_f16(acc[i][j], a4[i], &bh[j * 2]);
        }
    }

    const int crow = lane >> 2, ccol = (lane & 3) * 2;
    #pragma unroll
    for (int i = 0; i < 4; i++)
        #pragma unroll
        for (int j = 0; j < 2; j++)
            #pragma unroll
            for (int half = 0; half < 2; half++) {
                const int m = bm + wm + i * 16 + crow + half * 8;
                const int n = bn + wn + j * 8 + ccol;
                float v0 = acc[i][j][half * 2 + 0] + bias[n];
                float v1 = acc[i][j][half * 2 + 1] + bias[n + 1];
                if (OUT == 0) {
                    float2 r = { v0, v1 };
                    *reinterpret_cast<float2*>(&Cf[(size_t)m * N + n]) = r;
                } else {
                    const size_t om = (size_t)(m % TT) * BB + (size_t)(m / TT);
                    __half2 hp = { __float2half_rn(v0), __float2half_rn(v1) };
                    *reinterpret_cast<__half2*>(&Ch[om * N + n]) = hp;
                }
            }
}

// ---------------------------------------------------------------------------
// persistent RNN recurrence: W_hh single fp16 SMEM-RESIDENT; per-bm-group
// barriers; t=0 GEMM skipped. ROUND-13 CHANGE: K-chunk = 64 (16 syncs/step
// instead of 32; 4x deeper straight-line block per sync).
// smem: W 128KB + 3 x 16KB A stages = 176KB.
// ---------------------------------------------------------------------------
constexpr unsigned GRP_CTAS = HH / BN;              // 16
constexpr int BKR = 64;
constexpr int RNN_W_BYTES = BN * HH * 2;            // 131072
constexpr int RNN_A_STAGE = BM * BKR * 2;           // 16384
constexpr int RNN_SMEM = RNN_W_BYTES + STAGES * RNN_A_STAGE;  // 180224

__device__ __forceinline__ void group_barrier(int gid, unsigned target) {
    __syncthreads();
    if (threadIdx.x == 0) {
        __threadfence();
        unsigned arrived = atomicAdd(&g_barg[gid][0], 1u);
        if (arrived == GRP_CTAS - 1) {
            atomicExch(&g_barg[gid][0], 0u);
            __threadfence();
            atomicAdd(&g_barg[gid][1], 1u);
        } else {
            unsigned gg;
            do {
                asm volatile("ld.acquire.gpu.u32 %0, [%1];"
                             : "=r"(gg) : "l"(&g_barg[gid][1]) : "memory");
            } while ((int)(gg - target) < 0);
        }
        __threadfence();
    }
    __syncthreads();
}

__global__ __launch_bounds__(256)
void rnn_persist(const __half* __restrict__ Whh,
                 const float* __restrict__ b_hh,
                 const __half* __restrict__ xproj) {
    extern __shared__ __align__(16) __half hsm[];
    const uint32_t WB = (uint32_t)__cvta_generic_to_shared(hsm);
    const uint32_t AB = WB + (uint32_t)RNN_W_BYTES;
    const int tid = threadIdx.x, lane = tid & 31, wid = tid >> 5;
    const int bm = blockIdx.y * BM, bn = blockIdx.x * BN;
    const int gid = blockIdx.y;
    const int warp_m = wid >> 1, warp_n = wid & 1;   // 4 x 2
    const int wm = warp_m * 32, wn = warp_n * 32;
    constexpr int CH = HH / BKR;                      // 16

    unsigned gen0 = 0;
    if (tid == 0)
        asm volatile("ld.acquire.gpu.u32 %0, [%1];"
                     : "=r"(gen0) : "l"(&g_barg[gid][1]) : "memory");

    // one-time: load W tile [BN x HH] into 8x8-tiled smem (8192 16B pieces)
    // matrix (nb, kb) at WB + (nb*128 + kb)*128
    for (int q = tid; q < BN * (HH / 8); q += 256) {
        const int n = q >> 7;
        const int kb = q & 127;
        const uint32_t dst = WB + (uint32_t)((((n >> 3) * 128 + kb) * 128) + (n & 7) * 16);
        cp16(dst, Whh + (size_t)(bn + n) * HH + kb * 8);
    }
    CP_COMMIT();

    // A-stage loader: 128 rows x 8 kb = 1024 16B pieces -> 4 per thread
    // matrix (rb, kb) at stage + (rb*8 + kb)*128
    auto load_A = [&](const __half* h, int k0, int s) {
        #pragma unroll
        for (int i = 0; i < 4; i++) {
            const int p = tid + i * 256;
            const int row = p >> 3, kb = p & 7;
            const uint32_t dst = AB + (uint32_t)(s * RNN_A_STAGE)
                + (uint32_t)(((((row >> 3) << 3) + kb) * 128) + (row & 7) * 16);
            cp16(dst, h + (size_t)(bm + row) * HH + k0 + kb * 8);
        }
    };

    const int g = lane >> 3, lr = lane & 7;
    // A: matrix (rb + (g&1), kb + (g>>1)); rb stride = 8*128 = 1024
    const uint32_t aoff_lane = (uint32_t)((g & 1) * 1024 + (g >> 1) * 128 + lr * 16);
    // B (W): matrix (nb + (g>>1), kb + (g&1)); nb stride = 128*128 = 16384
    const uint32_t boff_lane = (uint32_t)((g >> 1) * 16384 + (g & 1) * 128 + lr * 16);
    const uint32_t a_mb_base = (uint32_t)(warp_m * 4) * 1024;   // 4 rb per warp
    const uint32_t b_nb_base = (uint32_t)(warp_n * 4) * 16384;

    const int crow = lane >> 2, ccol = (lane & 3) * 2;

    // ---- step 0 (h0 = 0): h1 = tanh(b_hh + x0); no GEMM, overlaps W load ----
    {
        __half* Nxt = g_h[1];
        const __half* xrow = xproj;   // t = 0
        #pragma unroll
        for (int i = 0; i < 2; i++)
            #pragma unroll
            for (int j = 0; j < 4; j++)
                #pragma unroll
                for (int half = 0; half < 2; half++) {
                    const int m = bm + wm + i * 16 + crow + half * 8;
                    const int n = bn + wn + j * 8 + ccol;
                    __half2 av = *reinterpret_cast<const __half2*>(&xrow[(size_t)m * HH + n]);
                    float v0 = tanhf(b_hh[n]     + __half2float(av.x));
                    float v1 = tanhf(b_hh[n + 1] + __half2float(av.y));
                    __half2 hp = { __float2half_rn(v0), __float2half_rn(v1) };
                    *reinterpret_cast<__half2*>(&Nxt[(size_t)m * HH + n]) = hp;
                }
    }
    CP_WAIT(0);            // W tile resident
    group_barrier(gid, gen0 + 1);

    for (int t = 1; t < TT; t++) {
        const int cur = t & 1;
        const __half* Acur = g_h[cur];
        __half* Nxt = g_h[cur ^ 1];
        const __half* xrow = xproj + (size_t)t * BB * HH;

        float acc[2][4][4] = {};

        #pragma unroll
        for (int s = 0; s < STAGES - 1; s++) { load_A(Acur, s * BKR, s); CP_COMMIT(); }

        for (int c = 0; c < CH; c++) {
            CP_WAIT(STAGES - 2);
            __syncthreads();
            const int pc = c + STAGES - 1;
            if (pc < CH) load_A(Acur, pc * BKR, pc % STAGES);
            CP_COMMIT();

            const uint32_t stA = AB + (uint32_t)((c % STAGES) * RNN_A_STAGE);
            const uint32_t kbW = (uint32_t)(c * 8) * 128;   // 8 kb per chunk
            #pragma unroll
            for (int kk = 0; kk < 4; kk++) {                // 4 x k16 per chunk
                uint32_t a4[2][4], b4[2][4];
                #pragma unroll
                for (int i = 0; i < 2; i++)
                    ldsm_x4(a4[i], stA + a_mb_base + (uint32_t)(i * 2) * 1024
                                   + (uint32_t)(kk * 2) * 128 + aoff_lane);
                #pragma unroll
                for (int u = 0; u < 2; u++)
                    ldsm_x4(b4[u], WB + b_nb_base + (uint32_t)(u * 2) * 16384
                                   + kbW + (uint32_t)(kk * 2) * 128 + boff_lane);
                #pragma unroll
                for (int i = 0; i < 2; i++)
                    #pragma unroll
                    for (int j = 0; j < 4; j++)
                        mma_f16(acc[i][j], a4[i], &b4[j >> 1][(j & 1) * 2]);
            }
        }

        // epilogue: h_next = tanh(acc + b_hh + xproj[t]) -> single fp16
        #pragma unroll
        for (int i = 0; i < 2; i++)
            #pragma unroll
            for (int j = 0; j < 4; j++)
                #pragma unroll
                for (int half = 0; half < 2; half++) {
                    const int m = bm + wm + i * 16 + crow + half * 8;
                    const int n = bn + wn + j * 8 + ccol;
                    __half2 av = *reinterpret_cast<const __half2*>(&xrow[(size_t)m * HH + n]);
                    float v0 = tanhf(acc[i][j][half * 2 + 0] + b_hh[n]     + __half2float(av.x));
                    float v1 = tanhf(acc[i][j][half * 2 + 1] + b_hh[n + 1] + __half2float(av.y));
                    __half2 hp = { __float2half_rn(v0), __float2half_rn(v1) };
                    *reinterpret_cast<__half2*>(&Nxt[(size_t)m * HH + n]) = hp;
                }

        if (t + 1 < TT) group_barrier(gid, gen0 + (unsigned)(t + 1));
    }
}

// ---------------------------------------------------------------------------
// fused weight prep (R11): [0,512) transpose-split W_emb; [512,1024) split
// W_ih; [1024,2048) cvt W_hh; [2048,3072) cvt W_out
// ---------------------------------------------------------------------------
__global__ __launch_bounds__(256)
void wprep_kernel(const float* __restrict__ W_emb,
                  const float* __restrict__ W_ih,
                  const float* __restrict__ W_hh,
                  const float* __restrict__ W_out,
                  __nv_bfloat16* __restrict__ wembT_hi,
                  __nv_bfloat16* __restrict__ wembT_lo,
                  __nv_bfloat16* __restrict__ wih_hi,
                  __nv_bfloat16* __restrict__ wih_lo,
                  __half* __restrict__ whh,
                  __half* __restrict__ wout) {
    const int b = blockIdx.x;
    const int tid = threadIdx.x;
    if (b < 512) {
        __shared__ float t[32][33];
        const int v0 = (b & 31) * 32, e0 = (b >> 5) * 32;
        const int tx = tid & 31, ty = tid >> 5;
        for (int i = ty; i < 32; i += 8)
            t[i][tx] = W_emb[(size_t)(e0 + i) * VV + v0 + tx];
        __syncthreads();
        for (int i = ty; i < 32; i += 8) {
            float x = t[tx][i];
            __nv_bfloat16 h, l;
            bf16_split(x, h, l);
            size_t o = (size_t)(v0 + i) * EE + e0 + tx;
            wembT_hi[o] = h;
            wembT_lo[o] = l;
        }
    } else if (b < 1024) {
        const int idx = (b - 512) * 256 + tid;
        float4 v = reinterpret_cast<const float4*>(W_ih)[idx];
        __nv_bfloat162 hp0, hp1, lp0, lp1;
        bf16_split(v.x, hp0.x, lp0.x);
        bf16_split(v.y, hp0.y, lp0.y);
        bf16_split(v.z, hp1.x, lp1.x);
        bf16_split(v.w, hp1.y, lp1.y);
        reinterpret_cast<__nv_bfloat162*>(wih_hi)[idx * 2 + 0] = hp0;
        reinterpret_cast<__nv_bfloat162*>(wih_hi)[idx * 2 + 1] = hp1;
        reinterpret_cast<__nv_bfloat162*>(wih_lo)[idx * 2 + 0] = lp0;
        reinterpret_cast<__nv_bfloat162*>(wih_lo)[idx * 2 + 1] = lp1;
    } else {
        const bool is_hh = b < 2048;
        const int idx = (b - (is_hh ? 1024 : 2048)) * 256 + tid;
        const float* src = is_hh ? W_hh : W_out;
        __half* dst = is_hh ? whh : wout;
        float4 v = reinterpret_cast<const float4*>(src)[idx];
        __half2 p0 = { __float2half_rn(v.x), __float2half_rn(v.y) };
        __half2 p1 = { __float2half_rn(v.z), __float2half_rn(v.w) };
        reinterpret_cast<__half2*>(dst)[idx * 2 + 0] = p0;
        reinterpret_cast<__half2*>(dst)[idx * 2 + 1] = p1;
    }
}

// bf[h] = sum_e W_ih[h,e] * b_emb[e] + b_ih[h]
__global__ void bfused_kernel(const float* __restrict__ W_ih,
                              const float* __restrict__ b_emb,
                              const float* __restrict__ b_ih,
                              float* __restrict__ out) {
    int h = blockIdx.x * blockDim.x + threadIdx.x;
    if (h >= HH) return;
    float s = b_ih[h];
    const float* row = W_ih + (size_t)h * EE;
    #pragma unroll 4
    for (int e = 0; e < EE; e++) s += row[e] * b_emb[e];
    out[h] = s;
}

__global__ void cvt_f16_kernel(const float* __restrict__ in,
                               __half* __restrict__ out, int n4) {
    int idx = blockIdx.x * blockDim.x + threadIdx.x;
    for (; idx < n4; idx += gridDim.x * blockDim.x) {
        float4 v = reinterpret_cast<const float4*>(in)[idx];
        __half2 p0 = { __float2half_rn(v.x), __float2half_rn(v.y) };
        __half2 p1 = { __float2half_rn(v.z), __float2half_rn(v.w) };
        reinterpret_cast<__half2*>(out)[idx * 2 + 0] = p0;
        reinterpret_cast<__half2*>(out)[idx * 2 + 1] = p1;
    }
}

// ---------------------------------------------------------------------------
extern "C" void kernel_launch(void* const* d_in, const int* in_sizes, int n_in,
                              void* d_out, int out_size) {
    const float* msg   = (const float*)d_in[0];
    const float* W_emb = (const float*)d_in[1];
    const float* b_emb = (const float*)d_in[2];
    const float* W_ih  = (const float*)d_in[3];
    const float* b_ih  = (const float*)d_in[4];
    const float* W_hh  = (const float*)d_in[5];
    const float* b_hh  = (const float*)d_in[6];
    const float* W_out = (const float*)d_in[7];
    const float* b_out = (const float*)d_in[8];
    float* out = (float*)d_out;

    float* bfused;
    __half *xproj, *msg_h, *wf, *whh, *wout, *hbuf;
    __nv_bfloat16 *wembT_hi, *wembT_lo, *wih_hi, *wih_lo;
    cudaGetSymbolAddress((void**)&bfused,   g_bfused);
    cudaGetSymbolAddress((void**)&xproj,    g_xproj);
    cudaGetSymbolAddress((void**)&msg_h,    g_msg_h);
    cudaGetSymbolAddress((void**)&wembT_hi, g_wembT_hi);
    cudaGetSymbolAddress((void**)&wembT_lo, g_wembT_lo);
    cudaGetSymbolAddress((void**)&wih_hi,   g_wih_hi);
    cudaGetSymbolAddress((void**)&wih_lo,   g_wih_lo);
    cudaGetSymbolAddress((void**)&wf,       g_wf);
    cudaGetSymbolAddress((void**)&whh,      g_whh);
    cudaGetSymbolAddress((void**)&wout,     g_wout);
    cudaGetSymbolAddress((void**)&hbuf,     g_h);

    constexpr int H1_SMEM = STAGES * (A_ELE + B_ELE) * 2;   // 46080
    cudaFuncSetAttribute(mma_gemm_bf3, cudaFuncAttributeMaxDynamicSharedMemorySize, BF3_SMEM);
    cudaFuncSetAttribute(mma_gemm_h<1>, cudaFuncAttributeMaxDynamicSharedMemorySize, H1_SMEM);
    cudaFuncSetAttribute(mma_gemm_h<0>, cudaFuncAttributeMaxDynamicSharedMemorySize, H1_SMEM);
    cudaFuncSetAttribute(rnn_persist, cudaFuncAttributeMaxDynamicSharedMemorySize, RNN_SMEM);

    // launch #1: all weight preps fused
    wprep_kernel<<<3072, 256>>>(W_emb, W_ih, W_hh, W_out,
                                wembT_hi, wembT_lo, wih_hi, wih_lo, whh, wout);
    // launch #2
    bfused_kernel<<<(HH + 255) / 256, 256>>>(W_ih, b_emb, b_ih, bfused);
    // launch #3
    cvt_f16_kernel<<<8192, 256>>>(msg, msg_h, BB * TT * VV / 4);

    // launch #4: W_fused = W_ih @ W_emb  (bf16 3-term, fp16 out)
    mma_gemm_bf3<<<dim3(VV / BN, HH / BM), 256, BF3_SMEM>>>(
        wih_hi, wih_lo, wembT_hi, wembT_lo, wf, HH, VV, EE);

    // launch #5: x_proj = msg @ W_fused^T + b_fused -> fp16, scatter
    mma_gemm_h<1><<<dim3(HH / BN, (BB * TT) / BM), 256, H1_SMEM>>>(
        msg_h, wf, bfused, nullptr, xproj, BB * TT, HH, VV);

    // launch #6 (ncu profiles this): persistent recurrence, BK=64
    rnn_persist<<<dim3(HH / BN, BB / BM), 256, RNN_SMEM>>>(whh, b_hh, xproj);

    // launch #7: out = h_T @ W_out^T + b_out
    mma_gemm_h<0><<<dim3(OO / BN, BB / BM), 256, H1_SMEM>>>(
        hbuf, wout, b_out, out, nullptr, BB, OO, HH);
}

// round 14
// speedup vs baseline: 1.0698x; 1.0698x over previous
#include <cuda_runtime.h>
#include <cuda_bf16.h>
#include <cuda_fp16.h>
#include <cstddef>
#include <cstdint>

#define BB   1024
#define TT   32
#define VV   1024
#define EE   512
#define HH   1024
#define OO   1024

// ---------------- device scratch (no runtime allocation) -------------------
__device__ float g_bfused[HH];
__device__ __half g_xproj[TT * BB * HH];     // fp16, bias folded in
__device__ __half g_msg_h[BB * TT * VV];
__device__ __nv_bfloat16 g_wembT_hi[VV * EE];
__device__ __nv_bfloat16 g_wembT_lo[VV * EE];
__device__ __nv_bfloat16 g_wih_hi[HH * EE];
__device__ __nv_bfloat16 g_wih_lo[HH * EE];
__device__ __half g_wf[HH * VV];             // W_fused, single fp16
__device__ __half g_whh[HH * HH];            // W_hh, single fp16
__device__ __half g_wout[OO * HH];           // W_out, single fp16
__device__ __half g_h[2][BB * HH];           // hidden state, single fp16
// per-bm-group barriers: [gid][0]=arrive count, [gid][1]=generation
// generation is monotonic across graph replays (targets are gen0-relative)
__device__ unsigned g_barg[8][2];

// ---------------- helpers ---------------------------------------------------
__device__ __forceinline__ void bf16_split(float x, __nv_bfloat16& h, __nv_bfloat16& l) {
    h = __float2bfloat16(x);
    l = __float2bfloat16(x - __bfloat162float(h));
}

__device__ __forceinline__ void ldsm_x4(uint32_t* r, uint32_t addr) {
    asm volatile("ldmatrix.sync.aligned.m8n8.x4.shared.b16 {%0,%1,%2,%3}, [%4];"
                 : "=r"(r[0]), "=r"(r[1]), "=r"(r[2]), "=r"(r[3]) : "r"(addr));
}

__device__ __forceinline__ void mma_bf16(float* d, const uint32_t* a, const uint32_t* b) {
    asm volatile("mma.sync.aligned.m16n8k16.row.col.f32.bf16.bf16.f32 "
                 "{%0,%1,%2,%3}, {%4,%5,%6,%7}, {%8,%9}, {%0,%1,%2,%3};"
                 : "+f"(d[0]), "+f"(d[1]), "+f"(d[2]), "+f"(d[3])
                 : "r"(a[0]), "r"(a[1]), "r"(a[2]), "r"(a[3]),
                   "r"(b[0]), "r"(b[1]));
}

__device__ __forceinline__ void mma_f16(float* d, const uint32_t* a, const uint32_t* b) {
    asm volatile("mma.sync.aligned.m16n8k16.row.col.f32.f16.f16.f32 "
                 "{%0,%1,%2,%3}, {%4,%5,%6,%7}, {%8,%9}, {%0,%1,%2,%3};"
                 : "+f"(d[0]), "+f"(d[1]), "+f"(d[2]), "+f"(d[3])
                 : "r"(a[0]), "r"(a[1]), "r"(a[2]), "r"(a[3]),
                   "r"(b[0]), "r"(b[1]));
}

__device__ __forceinline__ void cp16(uint32_t dst, const void* src) {
    asm volatile("cp.async.cg.shared.global [%0], [%1], 16;" :: "r"(dst), "l"(src));
}
#define CP_COMMIT() asm volatile("cp.async.commit_group;" ::: "memory")
#define CP_WAIT(n)  asm volatile("cp.async.wait_group %0;" :: "n"(n) : "memory")

// ---------------- tiling constants ------------------------------------------
constexpr int BM = 128, BN = 64, BK = 32, LDT = BK + 8, STAGES = 3;
constexpr int A_ELE = BM * LDT;                 // 5120
constexpr int B_ELE = BN * LDT;                 // 2560
constexpr int BF3_STG = 2 * A_ELE + 2 * B_ELE;
constexpr int BF3_SMEM = STAGES * BF3_STG * 2;
#define OFF_AHI 0
#define OFF_ALO (A_ELE)
#define OFF_BHI (2 * A_ELE)
#define OFF_BLO (2 * A_ELE + B_ELE)

// ---------------------------------------------------------------------------
// bf16 3-term GEMM (only for W_fused = W_ih @ W_emb, output single fp16)
// ---------------------------------------------------------------------------
__global__ __launch_bounds__(256)
void mma_gemm_bf3(const __nv_bfloat16* __restrict__ Ahi,
                  const __nv_bfloat16* __restrict__ Alo,
                  const __nv_bfloat16* __restrict__ Bhi,
                  const __nv_bfloat16* __restrict__ Blo,
                  __half* __restrict__ Cout,
                  int M, int N, int K) {
    extern __shared__ __align__(16) __nv_bfloat16 smem[];
    const uint32_t sb = (uint32_t)__cvta_generic_to_shared(smem);
    const int tid = threadIdx.x, lane = tid & 31, wid = tid >> 5;
    const int bm = blockIdx.y * BM, bn = blockIdx.x * BN;
    const int wm = (wid >> 2) * 64, wn = (wid & 3) * 16;
    const int CH = K / BK;

    const int a_r0 = tid >> 2, a_c = (tid & 3) * 8;
    const int a_r1 = (tid + 256) >> 2;
    const int b_r = tid >> 2;

    auto load_chunk = [&](int k0, int s) {
        const uint32_t st = sb + (uint32_t)(s * BF3_STG) * 2;
        const size_t ga0 = (size_t)(bm + a_r0) * K + k0 + a_c;
        const size_t ga1 = (size_t)(bm + a_r1) * K + k0 + a_c;
        const size_t gb  = (size_t)(bn + b_r ) * K + k0 + a_c;
        const uint32_t d0 = (uint32_t)(a_r0 * LDT + a_c) * 2;
        const uint32_t d1 = (uint32_t)(a_r1 * LDT + a_c) * 2;
        const uint32_t db = (uint32_t)(b_r  * LDT + a_c) * 2;
        cp16(st + OFF_AHI * 2 + d0, Ahi + ga0);
        cp16(st + OFF_AHI * 2 + d1, Ahi + ga1);
        cp16(st + OFF_ALO * 2 + d0, Alo + ga0);
        cp16(st + OFF_ALO * 2 + d1, Alo + ga1);
        cp16(st + OFF_BHI * 2 + db, Bhi + gb);
        cp16(st + OFF_BLO * 2 + db, Blo + gb);
    };

    const int a_row = wm + (lane & 7) + ((lane >> 3) & 1) * 8;
    const int a_col = (lane >> 4) * 8;
    const int b_row = wn + (lane >> 4) * 8 + (lane & 7);
    const int b_col = ((lane >> 3) & 1) * 8;
    const uint32_t aoff = (uint32_t)(a_row * LDT + a_col) * 2;
    const uint32_t boff = (uint32_t)(b_row * LDT + b_col) * 2;

    float acc[4][2][4] = {};

    #pragma unroll
    for (int s = 0; s < STAGES - 1; s++) { load_chunk(s * BK, s); CP_COMMIT(); }

    for (int c = 0; c < CH; c++) {
        CP_WAIT(STAGES - 2);
        __syncthreads();
        const int pc = c + STAGES - 1;
        if (pc < CH) load_chunk(pc * BK, pc % STAGES);
        CP_COMMIT();

        const uint32_t st = sb + (uint32_t)((c % STAGES) * BF3_STG) * 2;
        #pragma unroll
        for (int kk = 0; kk < BK; kk += 16) {
            uint32_t ah[4][4], al[4][4], bh[4], bl[4];
            #pragma unroll
            for (int i = 0; i < 4; i++) {
                ldsm_x4(ah[i], st + OFF_AHI * 2 + aoff + (uint32_t)(i * 16 * LDT + kk) * 2);
                ldsm_x4(al[i], st + OFF_ALO * 2 + aoff + (uint32_t)(i * 16 * LDT + kk) * 2);
            }
            ldsm_x4(bh, st + OFF_BHI * 2 + boff + (uint32_t)kk * 2);
            ldsm_x4(bl, st + OFF_BLO * 2 + boff + (uint32_t)kk * 2);
            #pragma unroll
            for (int i = 0; i < 4; i++)
                #pragma unroll
                for (int j = 0; j < 2; j++) {
                    mma_bf16(acc[i][j], ah[i], &bh[j * 2]);
                    mma_bf16(acc[i][j], ah[i], &bl[j * 2]);
                    mma_bf16(acc[i][j], al[i], &bh[j * 2]);
                }
        }
    }

    const int crow = lane >> 2, ccol = (lane & 3) * 2;
    #pragma unroll
    for (int i = 0; i < 4; i++)
        #pragma unroll
        for (int j = 0; j < 2; j++)
            #pragma unroll
            for (int half = 0; half < 2; half++) {
                const int m = bm + wm + i * 16 + crow + half * 8;
                const int n = bn + wn + j * 8 + ccol;
                __half2 hp = { __float2half_rn(acc[i][j][half * 2 + 0]),
                               __float2half_rn(acc[i][j][half * 2 + 1]) };
                *reinterpret_cast<__half2*>(&Cout[(size_t)m * N + n]) = hp;
            }
}

// ---------------------------------------------------------------------------
// fp16 GEMM (padded layout), 1 B plane:
//   OUT 0: fp32 out, no scatter          (out = h @ W_out^T + b_out)
//   OUT 1: fp16 out, scatter m -> (m%TT)*BB + m/TT   (x_proj)
// ---------------------------------------------------------------------------
template <int OUT>
__global__ __launch_bounds__(256)
void mma_gemm_h(const __half* __restrict__ A,
                const __half* __restrict__ Bhi,
                const float* __restrict__ bias,
                float* __restrict__ Cf,
                __half* __restrict__ Ch,
                int M, int N, int K) {
    constexpr int STG = A_ELE + B_ELE;
    extern __shared__ __align__(16) __half hsmem[];
    const uint32_t sb = (uint32_t)__cvta_generic_to_shared(hsmem);
    const int tid = threadIdx.x, lane = tid & 31, wid = tid >> 5;
    const int bm = blockIdx.y * BM, bn = blockIdx.x * BN;
    const int wm = (wid >> 2) * 64, wn = (wid & 3) * 16;
    const int CH = K / BK;

    const int a_r0 = tid >> 2, a_c = (tid & 3) * 8;
    const int a_r1 = (tid + 256) >> 2;
    const int b_r = tid >> 2;

    auto load_chunk = [&](int k0, int s) {
        const uint32_t st = sb + (uint32_t)(s * STG) * 2;
        const size_t ga0 = (size_t)(bm + a_r0) * K + k0 + a_c;
        const size_t ga1 = (size_t)(bm + a_r1) * K + k0 + a_c;
        const size_t gb  = (size_t)(bn + b_r ) * K + k0 + a_c;
        const uint32_t d0 = (uint32_t)(a_r0 * LDT + a_c) * 2;
        const uint32_t d1 = (uint32_t)(a_r1 * LDT + a_c) * 2;
        const uint32_t db = (uint32_t)(b_r  * LDT + a_c) * 2;
        cp16(st + d0, A + ga0);
        cp16(st + d1, A + ga1);
        cp16(st + (uint32_t)A_ELE * 2 + db, Bhi + gb);
    };

    const int a_row = wm + (lane & 7) + ((lane >> 3) & 1) * 8;
    const int a_col = (lane >> 4) * 8;
    const int b_row = wn + (lane >> 4) * 8 + (lane & 7);
    const int b_col = ((lane >> 3) & 1) * 8;
    const uint32_t aoff = (uint32_t)(a_row * LDT + a_col) * 2;
    const uint32_t boff = (uint32_t)(b_row * LDT + b_col) * 2;

    float acc[4][2][4] = {};

    #pragma unroll
    for (int s = 0; s < STAGES - 1; s++) { load_chunk(s * BK, s); CP_COMMIT(); }

    for (int c = 0; c < CH; c++) {
        CP_WAIT(STAGES - 2);
        __syncthreads();
        const int pc = c + STAGES - 1;
        if (pc < CH) load_chunk(pc * BK, pc % STAGES);
        CP_COMMIT();

        const uint32_t st = sb + (uint32_t)((c % STAGES) * STG) * 2;
        #pragma unroll
        for (int kk = 0; kk < BK; kk += 16) {
            uint32_t a4[4][4], bh[4];
            #pragma unroll
            for (int i = 0; i < 4; i++)
                ldsm_x4(a4[i], st + aoff + (uint32_t)(i * 16 * LDT + kk) * 2);
            ldsm_x4(bh, st + (uint32_t)A_ELE * 2 + boff + (uint32_t)kk * 2);
            #pragma unroll
            for (int i = 0; i < 4; i++)
                #pragma unroll
                for (int j = 0; j < 2; j++)
                    mma_f16(acc[i][j], a4[i], &bh[j * 2]);
        }
    }

    const int crow = lane >> 2, ccol = (lane & 3) * 2;
    #pragma unroll
    for (int i = 0; i < 4; i++)
        #pragma unroll
        for (int j = 0; j < 2; j++)
            #pragma unroll
            for (int half = 0; half < 2; half++) {
                const int m = bm + wm + i * 16 + crow + half * 8;
                const int n = bn + wn + j * 8 + ccol;
                float v0 = acc[i][j][half * 2 + 0] + bias[n];
                float v1 = acc[i][j][half * 2 + 1] + bias[n + 1];
                if (OUT == 0) {
                    float2 r = { v0, v1 };
                    *reinterpret_cast<float2*>(&Cf[(size_t)m * N + n]) = r;
                } else {
                    const size_t om = (size_t)(m % TT) * BB + (size_t)(m / TT);
                    __half2 hp = { __float2half_rn(v0), __float2half_rn(v1) };
                    *reinterpret_cast<__half2*>(&Ch[om * N + n]) = hp;
                }
            }
}

// ---------------------------------------------------------------------------
// persistent RNN recurrence: W_hh single fp16 SMEM-RESIDENT; per-bm-group
// barriers; t=0 GEMM skipped.  ROUND-14 CHANGE: 512 threads (16 warps, 4x4
// warp grid, 32x16 warp tiles) -> 4 warps/SMSP for latency hiding. BK=32.
// smem: W 128KB + 3 x 8KB A stages = 152KB (1 CTA/SM; 128 CTAs co-resident).
// ---------------------------------------------------------------------------
constexpr unsigned GRP_CTAS = HH / BN;              // 16
constexpr int RNN_W_BYTES = BN * HH * 2;            // 131072
constexpr int RNN_A_STAGE = BM * BK * 2;            // 8192
constexpr int RNN_SMEM = RNN_W_BYTES + STAGES * RNN_A_STAGE;  // 155648

__device__ __forceinline__ void group_barrier(int gid, unsigned target) {
    __syncthreads();
    if (threadIdx.x == 0) {
        __threadfence();
        unsigned arrived = atomicAdd(&g_barg[gid][0], 1u);
        if (arrived == GRP_CTAS - 1) {
            atomicExch(&g_barg[gid][0], 0u);
            __threadfence();
            atomicAdd(&g_barg[gid][1], 1u);
        } else {
            unsigned gg;
            do {
                asm volatile("ld.acquire.gpu.u32 %0, [%1];"
                             : "=r"(gg) : "l"(&g_barg[gid][1]) : "memory");
            } while ((int)(gg - target) < 0);
        }
        __threadfence();
    }
    __syncthreads();
}

__global__ __launch_bounds__(512)
void rnn_persist(const __half* __restrict__ Whh,
                 const float* __restrict__ b_hh,
                 const __half* __restrict__ xproj) {
    extern __shared__ __align__(16) __half hsm[];
    const uint32_t WB = (uint32_t)__cvta_generic_to_shared(hsm);
    const uint32_t AB = WB + (uint32_t)RNN_W_BYTES;
    const int tid = threadIdx.x, lane = tid & 31, wid = tid >> 5;   // wid 0..15
    const int bm = blockIdx.y * BM, bn = blockIdx.x * BN;
    const int gid = blockIdx.y;
    const int warp_m = wid >> 2, warp_n = wid & 3;   // 4 x 4
    const int wm = warp_m * 32, wn = warp_n * 16;
    constexpr int CH = HH / BK;                       // 32

    unsigned gen0 = 0;
    if (tid == 0)
        asm volatile("ld.acquire.gpu.u32 %0, [%1];"
                     : "=r"(gen0) : "l"(&g_barg[gid][1]) : "memory");

    // one-time: load W tile [BN x HH] into 8x8-tiled smem (8192 16B pieces)
    // matrix (nb, kb) at WB + (nb*128 + kb)*128
    for (int q = tid; q < BN * (HH / 8); q += 512) {
        const int n = q >> 7;
        const int kb = q & 127;
        const uint32_t dst = WB + (uint32_t)((((n >> 3) * 128 + kb) * 128) + (n & 7) * 16);
        cp16(dst, Whh + (size_t)(bn + n) * HH + kb * 8);
    }
    CP_COMMIT();

    // A-stage loader: 512 16B pieces -> exactly 1 per thread
    // matrix (rb, kb) at stage + (rb*4 + kb)*128
    auto load_A = [&](const __half* h, int k0, int s) {
        const int row = tid >> 2, kb = tid & 3;
        const uint32_t dst = AB + (uint32_t)(s * RNN_A_STAGE)
            + (uint32_t)(((((row >> 3) << 2) + kb) * 128) + (row & 7) * 16);
        cp16(dst, h + (size_t)(bm + row) * HH + k0 + kb * 8);
    };

    const int g = lane >> 3, lr = lane & 7;
    // A ldsm: matrix (rb + (g&1), kb + (g>>1)); rb stride = 4*128 = 512
    const uint32_t aoff_lane = (uint32_t)((g & 1) * 512 + (g >> 1) * 128 + lr * 16);
    // B ldsm: matrix (nb + (g>>1), kb + (g&1)); nb stride = 128*128 = 16384
    const uint32_t boff_lane = (uint32_t)((g >> 1) * 16384 + (g & 1) * 128 + lr * 16);
    const uint32_t a_mb_base = (uint32_t)(warp_m * 4) * 512;    // 4 rb per warp
    const uint32_t b_nb_base = (uint32_t)(warp_n * 2) * 16384;  // 2 nb per warp

    const int crow = lane >> 2, ccol = (lane & 3) * 2;

    // ---- step 0 (h0 = 0): h1 = tanh(b_hh + x0); no GEMM, overlaps W load ----
    {
        __half* Nxt = g_h[1];
        const __half* xrow = xproj;   // t = 0
        #pragma unroll
        for (int i = 0; i < 2; i++)
            #pragma unroll
            for (int j = 0; j < 2; j++)
                #pragma unroll
                for (int half = 0; half < 2; half++) {
                    const int m = bm + wm + i * 16 + crow + half * 8;
                    const int n = bn + wn + j * 8 + ccol;
                    __half2 av = *reinterpret_cast<const __half2*>(&xrow[(size_t)m * HH + n]);
                    float v0 = tanhf(b_hh[n]     + __half2float(av.x));
                    float v1 = tanhf(b_hh[n + 1] + __half2float(av.y));
                    __half2 hp = { __float2half_rn(v0), __float2half_rn(v1) };
                    *reinterpret_cast<__half2*>(&Nxt[(size_t)m * HH + n]) = hp;
                }
    }
    CP_WAIT(0);            // W tile resident
    group_barrier(gid, gen0 + 1);

    for (int t = 1; t < TT; t++) {
        const int cur = t & 1;
        const __half* Acur = g_h[cur];
        __half* Nxt = g_h[cur ^ 1];
        const __half* xrow = xproj + (size_t)t * BB * HH;

        float acc[2][2][4] = {};

        #pragma unroll
        for (int s = 0; s < STAGES - 1; s++) { load_A(Acur, s * BK, s); CP_COMMIT(); }

        for (int c = 0; c < CH; c++) {
            CP_WAIT(STAGES - 2);
            __syncthreads();
            const int pc = c + STAGES - 1;
            if (pc < CH) load_A(Acur, pc * BK, pc % STAGES);
            CP_COMMIT();

            const uint32_t stA = AB + (uint32_t)((c % STAGES) * RNN_A_STAGE);
            const uint32_t kbW = (uint32_t)(c * 4) * 128;   // 4 kb per chunk
            #pragma unroll
            for (int kk = 0; kk < 2; kk++) {
                uint32_t a4[2][4], b4[4];
                #pragma unroll
                for (int i = 0; i < 2; i++)
                    ldsm_x4(a4[i], stA + a_mb_base + (uint32_t)(i * 2) * 512
                                   + (uint32_t)(kk * 2) * 128 + aoff_lane);
                ldsm_x4(b4, WB + b_nb_base + kbW + (uint32_t)(kk * 2) * 128 + boff_lane);
                #pragma unroll
                for (int i = 0; i < 2; i++)
                    #pragma unroll
                    for (int j = 0; j < 2; j++)
                        mma_f16(acc[i][j], a4[i], &b4[j * 2]);
            }
        }

        // epilogue: h_next = tanh(acc + b_hh + xproj[t]) -> single fp16
        #pragma unroll
        for (int i = 0; i < 2; i++)
            #pragma unroll
            for (int j = 0; j < 2; j++)
                #pragma unroll
                for (int half = 0; half < 2; half++) {
                    const int m = bm + wm + i * 16 + crow + half * 8;
                    const int n = bn + wn + j * 8 + ccol;
                    __half2 av = *reinterpret_cast<const __half2*>(&xrow[(size_t)m * HH + n]);
                    float v0 = tanhf(acc[i][j][half * 2 + 0] + b_hh[n]     + __half2float(av.x));
                    float v1 = tanhf(acc[i][j][half * 2 + 1] + b_hh[n + 1] + __half2float(av.y));
                    __half2 hp = { __float2half_rn(v0), __float2half_rn(v1) };
                    *reinterpret_cast<__half2*>(&Nxt[(size_t)m * HH + n]) = hp;
                }

        if (t + 1 < TT) group_barrier(gid, gen0 + (unsigned)(t + 1));
    }
}

// ---------------------------------------------------------------------------
// fused weight prep (R11): [0,512) transpose-split W_emb; [512,1024) split
// W_ih; [1024,2048) cvt W_hh; [2048,3072) cvt W_out
// ---------------------------------------------------------------------------
__global__ __launch_bounds__(256)
void wprep_kernel(const float* __restrict__ W_emb,
                  const float* __restrict__ W_ih,
                  const float* __restrict__ W_hh,
                  const float* __restrict__ W_out,
                  __nv_bfloat16* __restrict__ wembT_hi,
                  __nv_bfloat16* __restrict__ wembT_lo,
                  __nv_bfloat16* __restrict__ wih_hi,
                  __nv_bfloat16* __restrict__ wih_lo,
                  __half* __restrict__ whh,
                  __half* __restrict__ wout) {
    const int b = blockIdx.x;
    const int tid = threadIdx.x;
    if (b < 512) {
        __shared__ float t[32][33];
        const int v0 = (b & 31) * 32, e0 = (b >> 5) * 32;
        const int tx = tid & 31, ty = tid >> 5;
        for (int i = ty; i < 32; i += 8)
            t[i][tx] = W_emb[(size_t)(e0 + i) * VV + v0 + tx];
        __syncthreads();
        for (int i = ty; i < 32; i += 8) {
            float x = t[tx][i];
            __nv_bfloat16 h, l;
            bf16_split(x, h, l);
            size_t o = (size_t)(v0 + i) * EE + e0 + tx;
            wembT_hi[o] = h;
            wembT_lo[o] = l;
        }
    } else if (b < 1024) {
        const int idx = (b - 512) * 256 + tid;
        float4 v = reinterpret_cast<const float4*>(W_ih)[idx];
        __nv_bfloat162 hp0, hp1, lp0, lp1;
        bf16_split(v.x, hp0.x, lp0.x);
        bf16_split(v.y, hp0.y, lp0.y);
        bf16_split(v.z, hp1.x, lp1.x);
        bf16_split(v.w, hp1.y, lp1.y);
        reinterpret_cast<__nv_bfloat162*>(wih_hi)[idx * 2 + 0] = hp0;
        reinterpret_cast<__nv_bfloat162*>(wih_hi)[idx * 2 + 1] = hp1;
        reinterpret_cast<__nv_bfloat162*>(wih_lo)[idx * 2 + 0] = lp0;
        reinterpret_cast<__nv_bfloat162*>(wih_lo)[idx * 2 + 1] = lp1;
    } else {
        const bool is_hh = b < 2048;
        const int idx = (b - (is_hh ? 1024 : 2048)) * 256 + tid;
        const float* src = is_hh ? W_hh : W_out;
        __half* dst = is_hh ? whh : wout;
        float4 v = reinterpret_cast<const float4*>(src)[idx];
        __half2 p0 = { __float2half_rn(v.x), __float2half_rn(v.y) };
        __half2 p1 = { __float2half_rn(v.z), __float2half_rn(v.w) };
        reinterpret_cast<__half2*>(dst)[idx * 2 + 0] = p0;
        reinterpret_cast<__half2*>(dst)[idx * 2 + 1] = p1;
    }
}

// bf[h] = sum_e W_ih[h,e] * b_emb[e] + b_ih[h]
__global__ void bfused_kernel(const float* __restrict__ W_ih,
                              const float* __restrict__ b_emb,
                              const float* __restrict__ b_ih,
                              float* __restrict__ out) {
    int h = blockIdx.x * blockDim.x + threadIdx.x;
    if (h >= HH) return;
    float s = b_ih[h];
    const float* row = W_ih + (size_t)h * EE;
    #pragma unroll 4
    for (int e = 0; e < EE; e++) s += row[e] * b_emb[e];
    out[h] = s;
}

__global__ void cvt_f16_kernel(const float* __restrict__ in,
                               __half* __restrict__ out, int n4) {
    int idx = blockIdx.x * blockDim.x + threadIdx.x;
    for (; idx < n4; idx += gridDim.x * blockDim.x) {
        float4 v = reinterpret_cast<const float4*>(in)[idx];
        __half2 p0 = { __float2half_rn(v.x), __float2half_rn(v.y) };
        __half2 p1 = { __float2half_rn(v.z), __float2half_rn(v.w) };
        reinterpret_cast<__half2*>(out)[idx * 2 + 0] = p0;
        reinterpret_cast<__half2*>(out)[idx * 2 + 1] = p1;
    }
}

// ---------------------------------------------------------------------------
extern "C" void kernel_launch(void* const* d_in, const int* in_sizes, int n_in,
                              void* d_out, int out_size) {
    const float* msg   = (const float*)d_in[0];
    const float* W_emb = (const float*)d_in[1];
    const float* b_emb = (const float*)d_in[2];
    const float* W_ih  = (const float*)d_in[3];
    const float* b_ih  = (const float*)d_in[4];
    const float* W_hh  = (const float*)d_in[5];
    const float* b_hh  = (const float*)d_in[6];
    const float* W_out = (const float*)d_in[7];
    const float* b_out = (const float*)d_in[8];
    float* out = (float*)d_out;

    float* bfused;
    __half *xproj, *msg_h, *wf, *whh, *wout, *hbuf;
    __nv_bfloat16 *wembT_hi, *wembT_lo, *wih_hi, *wih_lo;
    cudaGetSymbolAddress((void**)&bfused,   g_bfused);
    cudaGetSymbolAddress((void**)&xproj,    g_xproj);
    cudaGetSymbolAddress((void**)&msg_h,    g_msg_h);
    cudaGetSymbolAddress((void**)&wembT_hi, g_wembT_hi);
    cudaGetSymbolAddress((void**)&wembT_lo, g_wembT_lo);
    cudaGetSymbolAddress((void**)&wih_hi,   g_wih_hi);
    cudaGetSymbolAddress((void**)&wih_lo,   g_wih_lo);
    cudaGetSymbolAddress((void**)&wf,       g_wf);
    cudaGetSymbolAddress((void**)&whh,      g_whh);
    cudaGetSymbolAddress((void**)&wout,     g_wout);
    cudaGetSymbolAddress((void**)&hbuf,     g_h);

    constexpr int H1_SMEM = STAGES * (A_ELE + B_ELE) * 2;   // 46080
    cudaFuncSetAttribute(mma_gemm_bf3, cudaFuncAttributeMaxDynamicSharedMemorySize, BF3_SMEM);
    cudaFuncSetAttribute(mma_gemm_h<1>, cudaFuncAttributeMaxDynamicSharedMemorySize, H1_SMEM);
    cudaFuncSetAttribute(mma_gemm_h<0>, cudaFuncAttributeMaxDynamicSharedMemorySize, H1_SMEM);
    cudaFuncSetAttribute(rnn_persist, cudaFuncAttributeMaxDynamicSharedMemorySize, RNN_SMEM);

    // launch #1: all weight preps fused
    wprep_kernel<<<3072, 256>>>(W_emb, W_ih, W_hh, W_out,
                                wembT_hi, wembT_lo, wih_hi, wih_lo, whh, wout);
    // launch #2
    bfused_kernel<<<(HH + 255) / 256, 256>>>(W_ih, b_emb, b_ih, bfused);
    // launch #3
    cvt_f16_kernel<<<8192, 256>>>(msg, msg_h, BB * TT * VV / 4);

    // launch #4: W_fused = W_ih @ W_emb  (bf16 3-term, fp16 out)
    mma_gemm_bf3<<<dim3(VV / BN, HH / BM), 256, BF3_SMEM>>>(
        wih_hi, wih_lo, wembT_hi, wembT_lo, wf, HH, VV, EE);

    // launch #5: x_proj = msg @ W_fused^T + b_fused -> fp16, scatter
    mma_gemm_h<1><<<dim3(HH / BN, (BB * TT) / BM), 256, H1_SMEM>>>(
        msg_h, wf, bfused, nullptr, xproj, BB * TT, HH, VV);

    // launch #6 (ncu profiles this): persistent recurrence, 512 threads
    rnn_persist<<<dim3(HH / BN, BB / BM), 512, RNN_SMEM>>>(whh, b_hh, xproj);

    // launch #7: out = h_T @ W_out^T + b_out
    mma_gemm_h<0><<<dim3(OO / BN, BB / BM), 256, H1_SMEM>>>(
        hbuf, wout, b_out, out, nullptr, BB, OO, HH);
}

// round 15
// speedup vs baseline: 1.0720x; 1.0020x over previous
#include <cuda_runtime.h>
#include <cuda_bf16.h>
#include <cuda_fp16.h>
#include <cstddef>
#include <cstdint>

#define BB   1024
#define TT   32
#define VV   1024
#define EE   512
#define HH   1024
#define OO   1024

// ---------------- device scratch (no runtime allocation) -------------------
__device__ float g_bfused[HH];
__device__ __half g_xproj[TT * BB * HH];     // fp16, bias folded in
__device__ __half g_msg_h[BB * TT * VV];
__device__ __nv_bfloat16 g_wembT_hi[VV * EE];
__device__ __nv_bfloat16 g_wembT_lo[VV * EE];
__device__ __nv_bfloat16 g_wih_hi[HH * EE];
__device__ __nv_bfloat16 g_wih_lo[HH * EE];
__device__ __half g_wf[HH * VV];             // W_fused, single fp16
__device__ __half g_whh[HH * HH];            // W_hh, single fp16
__device__ __half g_wout[OO * HH];           // W_out, single fp16
__device__ __half g_h[2][BB * HH];           // hidden state, single fp16
// per-bm-group barriers: [gid][0]=arrive count, [gid][1]=generation
// generation is monotonic across graph replays (targets are gen0-relative)
__device__ unsigned g_barg[8][2];

// ---------------- helpers ---------------------------------------------------
__device__ __forceinline__ void bf16_split(float x, __nv_bfloat16& h, __nv_bfloat16& l) {
    h = __float2bfloat16(x);
    l = __float2bfloat16(x - __bfloat162float(h));
}

__device__ __forceinline__ void ldsm_x4(uint32_t* r, uint32_t addr) {
    asm volatile("ldmatrix.sync.aligned.m8n8.x4.shared.b16 {%0,%1,%2,%3}, [%4];"
                 : "=r"(r[0]), "=r"(r[1]), "=r"(r[2]), "=r"(r[3]) : "r"(addr));
}

__device__ __forceinline__ void mma_bf16(float* d, const uint32_t* a, const uint32_t* b) {
    asm volatile("mma.sync.aligned.m16n8k16.row.col.f32.bf16.bf16.f32 "
                 "{%0,%1,%2,%3}, {%4,%5,%6,%7}, {%8,%9}, {%0,%1,%2,%3};"
                 : "+f"(d[0]), "+f"(d[1]), "+f"(d[2]), "+f"(d[3])
                 : "r"(a[0]), "r"(a[1]), "r"(a[2]), "r"(a[3]),
                   "r"(b[0]), "r"(b[1]));
}

__device__ __forceinline__ void mma_f16(float* d, const uint32_t* a, const uint32_t* b) {
    asm volatile("mma.sync.aligned.m16n8k16.row.col.f32.f16.f16.f32 "
                 "{%0,%1,%2,%3}, {%4,%5,%6,%7}, {%8,%9}, {%0,%1,%2,%3};"
                 : "+f"(d[0]), "+f"(d[1]), "+f"(d[2]), "+f"(d[3])
                 : "r"(a[0]), "r"(a[1]), "r"(a[2]), "r"(a[3]),
                   "r"(b[0]), "r"(b[1]));
}

__device__ __forceinline__ void cp16(uint32_t dst, const void* src) {
    asm volatile("cp.async.cg.shared.global [%0], [%1], 16;" :: "r"(dst), "l"(src));
}
#define CP_COMMIT() asm volatile("cp.async.commit_group;" ::: "memory")
#define CP_WAIT(n)  asm volatile("cp.async.wait_group %0;" :: "n"(n) : "memory")

// ---------------- tiling constants ------------------------------------------
constexpr int BM = 128, BN = 64, BK = 32, LDT = BK + 8, STAGES = 3;
constexpr int A_ELE = BM * LDT;                 // 5120
constexpr int B_ELE = BN * LDT;                 // 2560
constexpr int BF3_STG = 2 * A_ELE + 2 * B_ELE;
constexpr int BF3_SMEM = STAGES * BF3_STG * 2;
#define OFF_AHI 0
#define OFF_ALO (A_ELE)
#define OFF_BHI (2 * A_ELE)
#define OFF_BLO (2 * A_ELE + B_ELE)

// ---------------------------------------------------------------------------
// bf16 3-term GEMM (only for W_fused = W_ih @ W_emb, output single fp16)
// ---------------------------------------------------------------------------
__global__ __launch_bounds__(256)
void mma_gemm_bf3(const __nv_bfloat16* __restrict__ Ahi,
                  const __nv_bfloat16* __restrict__ Alo,
                  const __nv_bfloat16* __restrict__ Bhi,
                  const __nv_bfloat16* __restrict__ Blo,
                  __half* __restrict__ Cout,
                  int M, int N, int K) {
    extern __shared__ __align__(16) __nv_bfloat16 smem[];
    const uint32_t sb = (uint32_t)__cvta_generic_to_shared(smem);
    const int tid = threadIdx.x, lane = tid & 31, wid = tid >> 5;
    const int bm = blockIdx.y * BM, bn = blockIdx.x * BN;
    const int wm = (wid >> 2) * 64, wn = (wid & 3) * 16;
    const int CH = K / BK;

    const int a_r0 = tid >> 2, a_c = (tid & 3) * 8;
    const int a_r1 = (tid + 256) >> 2;
    const int b_r = tid >> 2;

    auto load_chunk = [&](int k0, int s) {
        const uint32_t st = sb + (uint32_t)(s * BF3_STG) * 2;
        const size_t ga0 = (size_t)(bm + a_r0) * K + k0 + a_c;
        const size_t ga1 = (size_t)(bm + a_r1) * K + k0 + a_c;
        const size_t gb  = (size_t)(bn + b_r ) * K + k0 + a_c;
        const uint32_t d0 = (uint32_t)(a_r0 * LDT + a_c) * 2;
        const uint32_t d1 = (uint32_t)(a_r1 * LDT + a_c) * 2;
        const uint32_t db = (uint32_t)(b_r  * LDT + a_c) * 2;
        cp16(st + OFF_AHI * 2 + d0, Ahi + ga0);
        cp16(st + OFF_AHI * 2 + d1, Ahi + ga1);
        cp16(st + OFF_ALO * 2 + d0, Alo + ga0);
        cp16(st + OFF_ALO * 2 + d1, Alo + ga1);
        cp16(st + OFF_BHI * 2 + db, Bhi + gb);
        cp16(st + OFF_BLO * 2 + db, Blo + gb);
    };

    const int a_row = wm + (lane & 7) + ((lane >> 3) & 1) * 8;
    const int a_col = (lane >> 4) * 8;
    const int b_row = wn + (lane >> 4) * 8 + (lane & 7);
    const int b_col = ((lane >> 3) & 1) * 8;
    const uint32_t aoff = (uint32_t)(a_row * LDT + a_col) * 2;
    const uint32_t boff = (uint32_t)(b_row * LDT + b_col) * 2;

    float acc[4][2][4] = {};

    #pragma unroll
    for (int s = 0; s < STAGES - 1; s++) { load_chunk(s * BK, s); CP_COMMIT(); }

    for (int c = 0; c < CH; c++) {
        CP_WAIT(STAGES - 2);
        __syncthreads();
        const int pc = c + STAGES - 1;
        if (pc < CH) load_chunk(pc * BK, pc % STAGES);
        CP_COMMIT();

        const uint32_t st = sb + (uint32_t)((c % STAGES) * BF3_STG) * 2;
        #pragma unroll
        for (int kk = 0; kk < BK; kk += 16) {
            uint32_t ah[4][4], al[4][4], bh[4], bl[4];
            #pragma unroll
            for (int i = 0; i < 4; i++) {
                ldsm_x4(ah[i], st + OFF_AHI * 2 + aoff + (uint32_t)(i * 16 * LDT + kk) * 2);
                ldsm_x4(al[i], st + OFF_ALO * 2 + aoff + (uint32_t)(i * 16 * LDT + kk) * 2);
            }
            ldsm_x4(bh, st + OFF_BHI * 2 + boff + (uint32_t)kk * 2);
            ldsm_x4(bl, st + OFF_BLO * 2 + boff + (uint32_t)kk * 2);
            #pragma unroll
            for (int i = 0; i < 4; i++)
                #pragma unroll
                for (int j = 0; j < 2; j++) {
                    mma_bf16(acc[i][j], ah[i], &bh[j * 2]);
                    mma_bf16(acc[i][j], ah[i], &bl[j * 2]);
                    mma_bf16(acc[i][j], al[i], &bh[j * 2]);
                }
        }
    }

    const int crow = lane >> 2, ccol = (lane & 3) * 2;
    #pragma unroll
    for (int i = 0; i < 4; i++)
        #pragma unroll
        for (int j = 0; j < 2; j++)
            #pragma unroll
            for (int half = 0; half < 2; half++) {
                const int m = bm + wm + i * 16 + crow + half * 8;
                const int n = bn + wn + j * 8 + ccol;
                __half2 hp = { __float2half_rn(acc[i][j][half * 2 + 0]),
                               __float2half_rn(acc[i][j][half * 2 + 1]) };
                *reinterpret_cast<__half2*>(&Cout[(size_t)m * N + n]) = hp;
            }
}

// ---------------------------------------------------------------------------
// fp16 GEMM (padded layout), 1 B plane:
//   OUT 0: fp32 out, no scatter          (out = h @ W_out^T + b_out)
//   OUT 1: fp16 out, scatter m -> (m%TT)*BB + m/TT   (x_proj)
// ---------------------------------------------------------------------------
template <int OUT>
__global__ __launch_bounds__(256)
void mma_gemm_h(const __half* __restrict__ A,
                const __half* __restrict__ Bhi,
                const float* __restrict__ bias,
                float* __restrict__ Cf,
                __half* __restrict__ Ch,
                int M, int N, int K) {
    constexpr int STG = A_ELE + B_ELE;
    extern __shared__ __align__(16) __half hsmem[];
    const uint32_t sb = (uint32_t)__cvta_generic_to_shared(hsmem);
    const int tid = threadIdx.x, lane = tid & 31, wid = tid >> 5;
    const int bm = blockIdx.y * BM, bn = blockIdx.x * BN;
    const int wm = (wid >> 2) * 64, wn = (wid & 3) * 16;
    const int CH = K / BK;

    const int a_r0 = tid >> 2, a_c = (tid & 3) * 8;
    const int a_r1 = (tid + 256) >> 2;
    const int b_r = tid >> 2;

    auto load_chunk = [&](int k0, int s) {
        const uint32_t st = sb + (uint32_t)(s * STG) * 2;
        const size_t ga0 = (size_t)(bm + a_r0) * K + k0 + a_c;
        const size_t ga1 = (size_t)(bm + a_r1) * K + k0 + a_c;
        const size_t gb  = (size_t)(bn + b_r ) * K + k0 + a_c;
        const uint32_t d0 = (uint32_t)(a_r0 * LDT + a_c) * 2;
        const uint32_t d1 = (uint32_t)(a_r1 * LDT + a_c) * 2;
        const uint32_t db = (uint32_t)(b_r  * LDT + a_c) * 2;
        cp16(st + d0, A + ga0);
        cp16(st + d1, A + ga1);
        cp16(st + (uint32_t)A_ELE * 2 + db, Bhi + gb);
    };

    const int a_row = wm + (lane & 7) + ((lane >> 3) & 1) * 8;
    const int a_col = (lane >> 4) * 8;
    const int b_row = wn + (lane >> 4) * 8 + (lane & 7);
    const int b_col = ((lane >> 3) & 1) * 8;
    const uint32_t aoff = (uint32_t)(a_row * LDT + a_col) * 2;
    const uint32_t boff = (uint32_t)(b_row * LDT + b_col) * 2;

    float acc[4][2][4] = {};

    #pragma unroll
    for (int s = 0; s < STAGES - 1; s++) { load_chunk(s * BK, s); CP_COMMIT(); }

    for (int c = 0; c < CH; c++) {
        CP_WAIT(STAGES - 2);
        __syncthreads();
        const int pc = c + STAGES - 1;
        if (pc < CH) load_chunk(pc * BK, pc % STAGES);
        CP_COMMIT();

        const uint32_t st = sb + (uint32_t)((c % STAGES) * STG) * 2;
        #pragma unroll
        for (int kk = 0; kk < BK; kk += 16) {
            uint32_t a4[4][4], bh[4];
            #pragma unroll
            for (int i = 0; i < 4; i++)
                ldsm_x4(a4[i], st + aoff + (uint32_t)(i * 16 * LDT + kk) * 2);
            ldsm_x4(bh, st + (uint32_t)A_ELE * 2 + boff + (uint32_t)kk * 2);
            #pragma unroll
            for (int i = 0; i < 4; i++)
                #pragma unroll
                for (int j = 0; j < 2; j++)
                    mma_f16(acc[i][j], a4[i], &bh[j * 2]);
        }
    }

    const int crow = lane >> 2, ccol = (lane & 3) * 2;
    #pragma unroll
    for (int i = 0; i < 4; i++)
        #pragma unroll
        for (int j = 0; j < 2; j++)
            #pragma unroll
            for (int half = 0; half < 2; half++) {
                const int m = bm + wm + i * 16 + crow + half * 8;
                const int n = bn + wn + j * 8 + ccol;
                float v0 = acc[i][j][half * 2 + 0] + bias[n];
                float v1 = acc[i][j][half * 2 + 1] + bias[n + 1];
                if (OUT == 0) {
                    float2 r = { v0, v1 };
                    *reinterpret_cast<float2*>(&Cf[(size_t)m * N + n]) = r;
                } else {
                    const size_t om = (size_t)(m % TT) * BB + (size_t)(m / TT);
                    __half2 hp = { __float2half_rn(v0), __float2half_rn(v1) };
                    *reinterpret_cast<__half2*>(&Ch[om * N + n]) = hp;
                }
            }
}

// ---------------------------------------------------------------------------
// persistent RNN recurrence (R11 champion config): W_hh single fp16
// SMEM-RESIDENT; per-bm-group barriers; t=0 GEMM skipped; 256 threads,
// 4x2 warps, 32x32 warp tiles, BK=32.
// ROUND-15 CHANGE (only): A pipeline 3 -> 4 stages (smem 152 -> 160 KB).
// ---------------------------------------------------------------------------
constexpr unsigned GRP_CTAS = HH / BN;              // 16
constexpr int RSTG = 4;                             // A-pipeline depth
constexpr int RNN_W_BYTES = BN * HH * 2;            // 131072
constexpr int RNN_A_STAGE = BM * BK * 2;            // 8192
constexpr int RNN_SMEM = RNN_W_BYTES + RSTG * RNN_A_STAGE;  // 163840

__device__ __forceinline__ void group_barrier(int gid, unsigned target) {
    __syncthreads();
    if (threadIdx.x == 0) {
        __threadfence();
        unsigned arrived = atomicAdd(&g_barg[gid][0], 1u);
        if (arrived == GRP_CTAS - 1) {
            atomicExch(&g_barg[gid][0], 0u);
            __threadfence();
            atomicAdd(&g_barg[gid][1], 1u);
        } else {
            unsigned gg;
            do {
                asm volatile("ld.acquire.gpu.u32 %0, [%1];"
                             : "=r"(gg) : "l"(&g_barg[gid][1]) : "memory");
            } while ((int)(gg - target) < 0);
        }
        __threadfence();
    }
    __syncthreads();
}

__global__ __launch_bounds__(256)
void rnn_persist(const __half* __restrict__ Whh,
                 const float* __restrict__ b_hh,
                 const __half* __restrict__ xproj) {
    extern __shared__ __align__(16) __half hsm[];
    const uint32_t WB = (uint32_t)__cvta_generic_to_shared(hsm);
    const uint32_t AB = WB + (uint32_t)RNN_W_BYTES;
    const int tid = threadIdx.x, lane = tid & 31, wid = tid >> 5;
    const int bm = blockIdx.y * BM, bn = blockIdx.x * BN;
    const int gid = blockIdx.y;
    const int warp_m = wid >> 1, warp_n = wid & 1;   // 4 x 2
    const int wm = warp_m * 32, wn = warp_n * 32;
    constexpr int CH = HH / BK;                       // 32

    unsigned gen0 = 0;
    if (tid == 0)
        asm volatile("ld.acquire.gpu.u32 %0, [%1];"
                     : "=r"(gen0) : "l"(&g_barg[gid][1]) : "memory");

    // one-time: load W tile [BN x HH] into 8x8-tiled smem (8192 16B pieces)
    for (int q = tid; q < BN * (HH / 8); q += 256) {
        const int n = q >> 7;
        const int kb = q & 127;
        const uint32_t dst = WB + (uint32_t)((((n >> 3) * 128 + kb) * 128) + (n & 7) * 16);
        cp16(dst, Whh + (size_t)(bn + n) * HH + kb * 8);
    }
    CP_COMMIT();

    auto load_A = [&](const __half* h, int k0, int s) {
        #pragma unroll
        for (int i = 0; i < 2; i++) {
            const int p = tid + i * 256;
            const int row = p >> 2, kb = p & 3;
            const uint32_t dst = AB + (uint32_t)(s * RNN_A_STAGE)
                + (uint32_t)(((((row >> 3) << 2) + kb) * 128) + (row & 7) * 16);
            cp16(dst, h + (size_t)(bm + row) * HH + k0 + kb * 8);
        }
    };

    const int g = lane >> 3, lr = lane & 7;
    const uint32_t aoff_lane = (uint32_t)((g & 1) * 512 + (g >> 1) * 128 + lr * 16);
    const uint32_t boff_lane = (uint32_t)((g >> 1) * 16384 + (g & 1) * 128 + lr * 16);
    const uint32_t a_mb_base = (uint32_t)(warp_m * 4) * 512;
    const uint32_t b_nb_base = (uint32_t)(warp_n * 4) * 16384;

    const int crow = lane >> 2, ccol = (lane & 3) * 2;

    // ---- step 0 (h0 = 0): h1 = tanh(b_hh + x0); no GEMM, overlaps W load ----
    {
        __half* Nxt = g_h[1];
        const __half* xrow = xproj;   // t = 0
        #pragma unroll
        for (int i = 0; i < 2; i++)
            #pragma unroll
            for (int j = 0; j < 4; j++)
                #pragma unroll
                for (int half = 0; half < 2; half++) {
                    const int m = bm + wm + i * 16 + crow + half * 8;
                    const int n = bn + wn + j * 8 + ccol;
                    __half2 av = *reinterpret_cast<const __half2*>(&xrow[(size_t)m * HH + n]);
                    float v0 = tanhf(b_hh[n]     + __half2float(av.x));
                    float v1 = tanhf(b_hh[n + 1] + __half2float(av.y));
                    __half2 hp = { __float2half_rn(v0), __float2half_rn(v1) };
                    *reinterpret_cast<__half2*>(&Nxt[(size_t)m * HH + n]) = hp;
                }
    }
    CP_WAIT(0);            // W tile resident
    group_barrier(gid, gen0 + 1);

    for (int t = 1; t < TT; t++) {
        const int cur = t & 1;
        const __half* Acur = g_h[cur];
        __half* Nxt = g_h[cur ^ 1];
        const __half* xrow = xproj + (size_t)t * BB * HH;

        float acc[2][4][4] = {};

        #pragma unroll
        for (int s = 0; s < RSTG - 1; s++) { load_A(Acur, s * BK, s); CP_COMMIT(); }

        for (int c = 0; c < CH; c++) {
            CP_WAIT(RSTG - 2);
            __syncthreads();
            const int pc = c + RSTG - 1;
            if (pc < CH) load_A(Acur, pc * BK, pc % RSTG);
            CP_COMMIT();

            const uint32_t stA = AB + (uint32_t)((c % RSTG) * RNN_A_STAGE);
            const uint32_t kbW = (uint32_t)(c * 4) * 128;
            #pragma unroll
            for (int kk = 0; kk < 2; kk++) {
                uint32_t a4[2][4], b4[2][4];
                #pragma unroll
                for (int i = 0; i < 2; i++)
                    ldsm_x4(a4[i], stA + a_mb_base + (uint32_t)(i * 2) * 512
                                   + (uint32_t)(kk * 2) * 128 + aoff_lane);
                #pragma unroll
                for (int u = 0; u < 2; u++)
                    ldsm_x4(b4[u], WB + b_nb_base + (uint32_t)(u * 2) * 16384
                                   + kbW + (uint32_t)(kk * 2) * 128 + boff_lane);
                #pragma unroll
                for (int i = 0; i < 2; i++)
                    #pragma unroll
                    for (int j = 0; j < 4; j++)
                        mma_f16(acc[i][j], a4[i], &b4[j >> 1][(j & 1) * 2]);
            }
        }

        // epilogue: h_next = tanh(acc + b_hh + xproj[t]) -> single fp16
        #pragma unroll
        for (int i = 0; i < 2; i++)
            #pragma unroll
            for (int j = 0; j < 4; j++)
                #pragma unroll
                for (int half = 0; half < 2; half++) {
                    const int m = bm + wm + i * 16 + crow + half * 8;
                    const int n = bn + wn + j * 8 + ccol;
                    __half2 av = *reinterpret_cast<const __half2*>(&xrow[(size_t)m * HH + n]);
                    float v0 = tanhf(acc[i][j][half * 2 + 0] + b_hh[n]     + __half2float(av.x));
                    float v1 = tanhf(acc[i][j][half * 2 + 1] + b_hh[n + 1] + __half2float(av.y));
                    __half2 hp = { __float2half_rn(v0), __float2half_rn(v1) };
                    *reinterpret_cast<__half2*>(&Nxt[(size_t)m * HH + n]) = hp;
                }

        if (t + 1 < TT) group_barrier(gid, gen0 + (unsigned)(t + 1));
    }
}

// ---------------------------------------------------------------------------
// fused weight prep (R11): [0,512) transpose-split W_emb; [512,1024) split
// W_ih; [1024,2048) cvt W_hh; [2048,3072) cvt W_out
// ---------------------------------------------------------------------------
__global__ __launch_bounds__(256)
void wprep_kernel(const float* __restrict__ W_emb,
                  const float* __restrict__ W_ih,
                  const float* __restrict__ W_hh,
                  const float* __restrict__ W_out,
                  __nv_bfloat16* __restrict__ wembT_hi,
                  __nv_bfloat16* __restrict__ wembT_lo,
                  __nv_bfloat16* __restrict__ wih_hi,
                  __nv_bfloat16* __restrict__ wih_lo,
                  __half* __restrict__ whh,
                  __half* __restrict__ wout) {
    const int b = blockIdx.x;
    const int tid = threadIdx.x;
    if (b < 512) {
        __shared__ float t[32][33];
        const int v0 = (b & 31) * 32, e0 = (b >> 5) * 32;
        const int tx = tid & 31, ty = tid >> 5;
        for (int i = ty; i < 32; i += 8)
            t[i][tx] = W_emb[(size_t)(e0 + i) * VV + v0 + tx];
        __syncthreads();
        for (int i = ty; i < 32; i += 8) {
            float x = t[tx][i];
            __nv_bfloat16 h, l;
            bf16_split(x, h, l);
            size_t o = (size_t)(v0 + i) * EE + e0 + tx;
            wembT_hi[o] = h;
            wembT_lo[o] = l;
        }
    } else if (b < 1024) {
        const int idx = (b - 512) * 256 + tid;
        float4 v = reinterpret_cast<const float4*>(W_ih)[idx];
        __nv_bfloat162 hp0, hp1, lp0, lp1;
        bf16_split(v.x, hp0.x, lp0.x);
        bf16_split(v.y, hp0.y, lp0.y);
        bf16_split(v.z, hp1.x, lp1.x);
        bf16_split(v.w, hp1.y, lp1.y);
        reinterpret_cast<__nv_bfloat162*>(wih_hi)[idx * 2 + 0] = hp0;
        reinterpret_cast<__nv_bfloat162*>(wih_hi)[idx * 2 + 1] = hp1;
        reinterpret_cast<__nv_bfloat162*>(wih_lo)[idx * 2 + 0] = lp0;
        reinterpret_cast<__nv_bfloat162*>(wih_lo)[idx * 2 + 1] = lp1;
    } else {
        const bool is_hh = b < 2048;
        const int idx = (b - (is_hh ? 1024 : 2048)) * 256 + tid;
        const float* src = is_hh ? W_hh : W_out;
        __half* dst = is_hh ? whh : wout;
        float4 v = reinterpret_cast<const float4*>(src)[idx];
        __half2 p0 = { __float2half_rn(v.x), __float2half_rn(v.y) };
        __half2 p1 = { __float2half_rn(v.z), __float2half_rn(v.w) };
        reinterpret_cast<__half2*>(dst)[idx * 2 + 0] = p0;
        reinterpret_cast<__half2*>(dst)[idx * 2 + 1] = p1;
    }
}

// bf[h] = sum_e W_ih[h,e] * b_emb[e] + b_ih[h]
__global__ void bfused_kernel(const float* __restrict__ W_ih,
                              const float* __restrict__ b_emb,
                              const float* __restrict__ b_ih,
                              float* __restrict__ out) {
    int h = blockIdx.x * blockDim.x + threadIdx.x;
    if (h >= HH) return;
    float s = b_ih[h];
    const float* row = W_ih + (size_t)h * EE;
    #pragma unroll 4
    for (int e = 0; e < EE; e++) s += row[e] * b_emb[e];
    out[h] = s;
}

__global__ void cvt_f16_kernel(const float* __restrict__ in,
                               __half* __restrict__ out, int n4) {
    int idx = blockIdx.x * blockDim.x + threadIdx.x;
    for (; idx < n4; idx += gridDim.x * blockDim.x) {
        float4 v = reinterpret_cast<const float4*>(in)[idx];
        __half2 p0 = { __float2half_rn(v.x), __float2half_rn(v.y) };
        __half2 p1 = { __float2half_rn(v.z), __float2half_rn(v.w) };
        reinterpret_cast<__half2*>(out)[idx * 2 + 0] = p0;
        reinterpret_cast<__half2*>(out)[idx * 2 + 1] = p1;
    }
}

// ---------------------------------------------------------------------------
extern "C" void kernel_launch(void* const* d_in, const int* in_sizes, int n_in,
                              void* d_out, int out_size) {
    const float* msg   = (const float*)d_in[0];
    const float* W_emb = (const float*)d_in[1];
    const float* b_emb = (const float*)d_in[2];
    const float* W_ih  = (const float*)d_in[3];
    const float* b_ih  = (const float*)d_in[4];
    const float* W_hh  = (const float*)d_in[5];
    const float* b_hh  = (const float*)d_in[6];
    const float* W_out = (const float*)d_in[7];
    const float* b_out = (const float*)d_in[8];
    float* out = (float*)d_out;

    float* bfused;
    __half *xproj, *msg_h, *wf, *whh, *wout, *hbuf;
    __nv_bfloat16 *wembT_hi, *wembT_lo, *wih_hi, *wih_lo;
    cudaGetSymbolAddress((void**)&bfused,   g_bfused);
    cudaGetSymbolAddress((void**)&xproj,    g_xproj);
    cudaGetSymbolAddress((void**)&msg_h,    g_msg_h);
    cudaGetSymbolAddress((void**)&wembT_hi, g_wembT_hi);
    cudaGetSymbolAddress((void**)&wembT_lo, g_wembT_lo);
    cudaGetSymbolAddress((void**)&wih_hi,   g_wih_hi);
    cudaGetSymbolAddress((void**)&wih_lo,   g_wih_lo);
    cudaGetSymbolAddress((void**)&wf,       g_wf);
    cudaGetSymbolAddress((void**)&whh,      g_whh);
    cudaGetSymbolAddress((void**)&wout,     g_wout);
    cudaGetSymbolAddress((void**)&hbuf,     g_h);

    constexpr int H1_SMEM = STAGES * (A_ELE + B_ELE) * 2;   // 46080
    cudaFuncSetAttribute(mma_gemm_bf3, cudaFuncAttributeMaxDynamicSharedMemorySize, BF3_SMEM);
    cudaFuncSetAttribute(mma_gemm_h<1>, cudaFuncAttributeMaxDynamicSharedMemorySize, H1_SMEM);
    cudaFuncSetAttribute(mma_gemm_h<0>, cudaFuncAttributeMaxDynamicSharedMemorySize, H1_SMEM);
    cudaFuncSetAttribute(rnn_persist, cudaFuncAttributeMaxDynamicSharedMemorySize, RNN_SMEM);

    // launch #1: all weight preps fused
    wprep_kernel<<<3072, 256>>>(W_emb, W_ih, W_hh, W_out,
                                wembT_hi, wembT_lo, wih_hi, wih_lo, whh, wout);
    // launch #2
    bfused_kernel<<<(HH + 255) / 256, 256>>>(W_ih, b_emb, b_ih, bfused);
    // launch #3
    cvt_f16_kernel<<<8192, 256>>>(msg, msg_h, BB * TT * VV / 4);

    // launch #4: W_fused = W_ih @ W_emb  (bf16 3-term, fp16 out)
    mma_gemm_bf3<<<dim3(VV / BN, HH / BM), 256, BF3_SMEM>>>(
        wih_hi, wih_lo, wembT_hi, wembT_lo, wf, HH, VV, EE);

    // launch #5: x_proj = msg @ W_fused^T + b_fused -> fp16, scatter
    mma_gemm_h<1><<<dim3(HH / BN, (BB * TT) / BM), 256, H1_SMEM>>>(
        msg_h, wf, bfused, nullptr, xproj, BB * TT, HH, VV);

    // launch #6: persistent recurrence (R11 config, 4-stage A pipeline)
    rnn_persist<<<dim3(HH / BN, BB / BM), 256, RNN_SMEM>>>(whh, b_hh, xproj);

    // launch #7: out = h_T @ W_out^T + b_out
    mma_gemm_h<0><<<dim3(OO / BN, BB / BM), 256, H1_SMEM>>>(
        hbuf, wout, b_out, out, nullptr, BB, OO, HH);
}

// round 16
// speedup vs baseline: 1.1038x; 1.0297x over previous
#include <cuda_runtime.h>
#include <cuda_bf16.h>
#include <cuda_fp16.h>
#include <cstddef>
#include <cstdint>

#define BB   1024
#define TT   32
#define VV   1024
#define EE   512
#define HH   1024
#define OO   1024

// ---------------- device scratch (no runtime allocation) -------------------
__device__ float g_bfused[HH];
__device__ __half g_xproj[TT * BB * HH];     // fp16, bias folded in
__device__ __half g_msg_h[BB * TT * VV];
__device__ __nv_bfloat16 g_wembT_hi[VV * EE];
__device__ __nv_bfloat16 g_wembT_lo[VV * EE];
__device__ __nv_bfloat16 g_wih_hi[HH * EE];
__device__ __nv_bfloat16 g_wih_lo[HH * EE];
__device__ __half g_wf[HH * VV];             // W_fused, single fp16
__device__ __half g_whh[HH * HH];            // W_hh, single fp16
__device__ __half g_wout[OO * HH];           // W_out, single fp16
__device__ __half g_h[2][BB * HH];           // hidden state, single fp16
// per-bm-group barriers: [gid][0]=arrive count, [gid][1]=generation
// generation is monotonic across graph replays (targets are gen0-relative)
__device__ unsigned g_barg[8][2];

// ---------------- helpers ---------------------------------------------------
__device__ __forceinline__ void bf16_split(float x, __nv_bfloat16& h, __nv_bfloat16& l) {
    h = __float2bfloat16(x);
    l = __float2bfloat16(x - __bfloat162float(h));
}

// fast tanh via MUFU exp: tanh(x) = (e^{2x}-1)/(e^{2x}+1); clamp avoids inf/inf
__device__ __forceinline__ float fast_tanh(float x) {
    x = fminf(9.0f, fmaxf(-9.0f, x));
    float e = __expf(2.0f * x);
    return __fdividef(e - 1.0f, e + 1.0f);
}

__device__ __forceinline__ void ldsm_x4(uint32_t* r, uint32_t addr) {
    asm volatile("ldmatrix.sync.aligned.m8n8.x4.shared.b16 {%0,%1,%2,%3}, [%4];"
                 : "=r"(r[0]), "=r"(r[1]), "=r"(r[2]), "=r"(r[3]) : "r"(addr));
}

__device__ __forceinline__ void mma_bf16(float* d, const uint32_t* a, const uint32_t* b) {
    asm volatile("mma.sync.aligned.m16n8k16.row.col.f32.bf16.bf16.f32 "
                 "{%0,%1,%2,%3}, {%4,%5,%6,%7}, {%8,%9}, {%0,%1,%2,%3};"
                 : "+f"(d[0]), "+f"(d[1]), "+f"(d[2]), "+f"(d[3])
                 : "r"(a[0]), "r"(a[1]), "r"(a[2]), "r"(a[3]),
                   "r"(b[0]), "r"(b[1]));
}

__device__ __forceinline__ void mma_f16(float* d, const uint32_t* a, const uint32_t* b) {
    asm volatile("mma.sync.aligned.m16n8k16.row.col.f32.f16.f16.f32 "
                 "{%0,%1,%2,%3}, {%4,%5,%6,%7}, {%8,%9}, {%0,%1,%2,%3};"
                 : "+f"(d[0]), "+f"(d[1]), "+f"(d[2]), "+f"(d[3])
                 : "r"(a[0]), "r"(a[1]), "r"(a[2]), "r"(a[3]),
                   "r"(b[0]), "r"(b[1]));
}

__device__ __forceinline__ void cp16(uint32_t dst, const void* src) {
    asm volatile("cp.async.cg.shared.global [%0], [%1], 16;" :: "r"(dst), "l"(src));
}
#define CP_COMMIT() asm volatile("cp.async.commit_group;" ::: "memory")
#define CP_WAIT(n)  asm volatile("cp.async.wait_group %0;" :: "n"(n) : "memory")

// ---------------- tiling constants ------------------------------------------
constexpr int BM = 128, BN = 64, BK = 32, LDT = BK + 8, STAGES = 3;
constexpr int A_ELE = BM * LDT;                 // 5120
constexpr int B_ELE = BN * LDT;                 // 2560
constexpr int BF3_STG = 2 * A_ELE + 2 * B_ELE;
constexpr int BF3_SMEM = STAGES * BF3_STG * 2;
#define OFF_AHI 0
#define OFF_ALO (A_ELE)
#define OFF_BHI (2 * A_ELE)
#define OFF_BLO (2 * A_ELE + B_ELE)

// ---------------------------------------------------------------------------
// bf16 3-term GEMM (only for W_fused = W_ih @ W_emb, output single fp16)
// ---------------------------------------------------------------------------
__global__ __launch_bounds__(256)
void mma_gemm_bf3(const __nv_bfloat16* __restrict__ Ahi,
                  const __nv_bfloat16* __restrict__ Alo,
                  const __nv_bfloat16* __restrict__ Bhi,
                  const __nv_bfloat16* __restrict__ Blo,
                  __half* __restrict__ Cout,
                  int M, int N, int K) {
    extern __shared__ __align__(16) __nv_bfloat16 smem[];
    const uint32_t sb = (uint32_t)__cvta_generic_to_shared(smem);
    const int tid = threadIdx.x, lane = tid & 31, wid = tid >> 5;
    const int bm = blockIdx.y * BM, bn = blockIdx.x * BN;
    const int wm = (wid >> 2) * 64, wn = (wid & 3) * 16;
    const int CH = K / BK;

    const int a_r0 = tid >> 2, a_c = (tid & 3) * 8;
    const int a_r1 = (tid + 256) >> 2;
    const int b_r = tid >> 2;

    auto load_chunk = [&](int k0, int s) {
        const uint32_t st = sb + (uint32_t)(s * BF3_STG) * 2;
        const size_t ga0 = (size_t)(bm + a_r0) * K + k0 + a_c;
        const size_t ga1 = (size_t)(bm + a_r1) * K + k0 + a_c;
        const size_t gb  = (size_t)(bn + b_r ) * K + k0 + a_c;
        const uint32_t d0 = (uint32_t)(a_r0 * LDT + a_c) * 2;
        const uint32_t d1 = (uint32_t)(a_r1 * LDT + a_c) * 2;
        const uint32_t db = (uint32_t)(b_r  * LDT + a_c) * 2;
        cp16(st + OFF_AHI * 2 + d0, Ahi + ga0);
        cp16(st + OFF_AHI * 2 + d1, Ahi + ga1);
        cp16(st + OFF_ALO * 2 + d0, Alo + ga0);
        cp16(st + OFF_ALO * 2 + d1, Alo + ga1);
        cp16(st + OFF_BHI * 2 + db, Bhi + gb);
        cp16(st + OFF_BLO * 2 + db, Blo + gb);
    };

    const int a_row = wm + (lane & 7) + ((lane >> 3) & 1) * 8;
    const int a_col = (lane >> 4) * 8;
    const int b_row = wn + (lane >> 4) * 8 + (lane & 7);
    const int b_col = ((lane >> 3) & 1) * 8;
    const uint32_t aoff = (uint32_t)(a_row * LDT + a_col) * 2;
    const uint32_t boff = (uint32_t)(b_row * LDT + b_col) * 2;

    float acc[4][2][4] = {};

    #pragma unroll
    for (int s = 0; s < STAGES - 1; s++) { load_chunk(s * BK, s); CP_COMMIT(); }

    for (int c = 0; c < CH; c++) {
        CP_WAIT(STAGES - 2);
        __syncthreads();
        const int pc = c + STAGES - 1;
        if (pc < CH) load_chunk(pc * BK, pc % STAGES);
        CP_COMMIT();

        const uint32_t st = sb + (uint32_t)((c % STAGES) * BF3_STG) * 2;
        #pragma unroll
        for (int kk = 0; kk < BK; kk += 16) {
            uint32_t ah[4][4], al[4][4], bh[4], bl[4];
            #pragma unroll
            for (int i = 0; i < 4; i++) {
                ldsm_x4(ah[i], st + OFF_AHI * 2 + aoff + (uint32_t)(i * 16 * LDT + kk) * 2);
                ldsm_x4(al[i], st + OFF_ALO * 2 + aoff + (uint32_t)(i * 16 * LDT + kk) * 2);
            }
            ldsm_x4(bh, st + OFF_BHI * 2 + boff + (uint32_t)kk * 2);
            ldsm_x4(bl, st + OFF_BLO * 2 + boff + (uint32_t)kk * 2);
            #pragma unroll
            for (int i = 0; i < 4; i++)
                #pragma unroll
                for (int j = 0; j < 2; j++) {
                    mma_bf16(acc[i][j], ah[i], &bh[j * 2]);
                    mma_bf16(acc[i][j], ah[i], &bl[j * 2]);
                    mma_bf16(acc[i][j], al[i], &bh[j * 2]);
                }
        }
    }

    const int crow = lane >> 2, ccol = (lane & 3) * 2;
    #pragma unroll
    for (int i = 0; i < 4; i++)
        #pragma unroll
        for (int j = 0; j < 2; j++)
            #pragma unroll
            for (int half = 0; half < 2; half++) {
                const int m = bm + wm + i * 16 + crow + half * 8;
                const int n = bn + wn + j * 8 + ccol;
                __half2 hp = { __float2half_rn(acc[i][j][half * 2 + 0]),
                               __float2half_rn(acc[i][j][half * 2 + 1]) };
                *reinterpret_cast<__half2*>(&Cout[(size_t)m * N + n]) = hp;
            }
}

// ---------------------------------------------------------------------------
// fp16 GEMM (padded layout), 1 B plane:
//   OUT 0: fp32 out, no scatter          (out = h @ W_out^T + b_out)
//   OUT 1: fp16 out, scatter m -> (m%TT)*BB + m/TT   (x_proj)
// ---------------------------------------------------------------------------
template <int OUT>
__global__ __launch_bounds__(256)
void mma_gemm_h(const __half* __restrict__ A,
                const __half* __restrict__ Bhi,
                const float* __restrict__ bias,
                float* __restrict__ Cf,
                __half* __restrict__ Ch,
                int M, int N, int K) {
    constexpr int STG = A_ELE + B_ELE;
    extern __shared__ __align__(16) __half hsmem[];
    const uint32_t sb = (uint32_t)__cvta_generic_to_shared(hsmem);
    const int tid = threadIdx.x, lane = tid & 31, wid = tid >> 5;
    const int bm = blockIdx.y * BM, bn = blockIdx.x * BN;
    const int wm = (wid >> 2) * 64, wn = (wid & 3) * 16;
    const int CH = K / BK;

    const int a_r0 = tid >> 2, a_c = (tid & 3) * 8;
    const int a_r1 = (tid + 256) >> 2;
    const int b_r = tid >> 2;

    auto load_chunk = [&](int k0, int s) {
        const uint32_t st = sb + (uint32_t)(s * STG) * 2;
        const size_t ga0 = (size_t)(bm + a_r0) * K + k0 + a_c;
        const size_t ga1 = (size_t)(bm + a_r1) * K + k0 + a_c;
        const size_t gb  = (size_t)(bn + b_r ) * K + k0 + a_c;
        const uint32_t d0 = (uint32_t)(a_r0 * LDT + a_c) * 2;
        const uint32_t d1 = (uint32_t)(a_r1 * LDT + a_c) * 2;
        const uint32_t db = (uint32_t)(b_r  * LDT + a_c) * 2;
        cp16(st + d0, A + ga0);
        cp16(st + d1, A + ga1);
        cp16(st + (uint32_t)A_ELE * 2 + db, Bhi + gb);
    };

    const int a_row = wm + (lane & 7) + ((lane >> 3) & 1) * 8;
    const int a_col = (lane >> 4) * 8;
    const int b_row = wn + (lane >> 4) * 8 + (lane & 7);
    const int b_col = ((lane >> 3) & 1) * 8;
    const uint32_t aoff = (uint32_t)(a_row * LDT + a_col) * 2;
    const uint32_t boff = (uint32_t)(b_row * LDT + b_col) * 2;

    float acc[4][2][4] = {};

    #pragma unroll
    for (int s = 0; s < STAGES - 1; s++) { load_chunk(s * BK, s); CP_COMMIT(); }

    for (int c = 0; c < CH; c++) {
        CP_WAIT(STAGES - 2);
        __syncthreads();
        const int pc = c + STAGES - 1;
        if (pc < CH) load_chunk(pc * BK, pc % STAGES);
        CP_COMMIT();

        const uint32_t st = sb + (uint32_t)((c % STAGES) * STG) * 2;
        #pragma unroll
        for (int kk = 0; kk < BK; kk += 16) {
            uint32_t a4[4][4], bh[4];
            #pragma unroll
            for (int i = 0; i < 4; i++)
                ldsm_x4(a4[i], st + aoff + (uint32_t)(i * 16 * LDT + kk) * 2);
            ldsm_x4(bh, st + (uint32_t)A_ELE * 2 + boff + (uint32_t)kk * 2);
            #pragma unroll
            for (int i = 0; i < 4; i++)
                #pragma unroll
                for (int j = 0; j < 2; j++)
                    mma_f16(acc[i][j], a4[i], &bh[j * 2]);
        }
    }

    const int crow = lane >> 2, ccol = (lane & 3) * 2;
    #pragma unroll
    for (int i = 0; i < 4; i++)
        #pragma unroll
        for (int j = 0; j < 2; j++)
            #pragma unroll
            for (int half = 0; half < 2; half++) {
                const int m = bm + wm + i * 16 + crow + half * 8;
                const int n = bn + wn + j * 8 + ccol;
                float v0 = acc[i][j][half * 2 + 0] + bias[n];
                float v1 = acc[i][j][half * 2 + 1] + bias[n + 1];
                if (OUT == 0) {
                    float2 r = { v0, v1 };
                    *reinterpret_cast<float2*>(&Cf[(size_t)m * N + n]) = r;
                } else {
                    const size_t om = (size_t)(m % TT) * BB + (size_t)(m / TT);
                    __half2 hp = { __float2half_rn(v0), __float2half_rn(v1) };
                    *reinterpret_cast<__half2*>(&Ch[om * N + n]) = hp;
                }
            }
}

// ---------------------------------------------------------------------------
// persistent RNN recurrence (EXACT R11 champion config): W_hh single fp16
// SMEM-RESIDENT; per-bm-group barriers; t=0 GEMM skipped; 256 threads,
// 4x2 warps, 32x32 warp tiles, BK=32, 3-stage A pipeline.
// ROUND-16 CHANGE (only): tanhf -> fast_tanh (MUFU exp) in epilogues.
// ---------------------------------------------------------------------------
constexpr unsigned GRP_CTAS = HH / BN;              // 16
constexpr int RNN_W_BYTES = BN * HH * 2;            // 131072
constexpr int RNN_A_STAGE = BM * BK * 2;            // 8192
constexpr int RNN_SMEM = RNN_W_BYTES + STAGES * RNN_A_STAGE;  // 155648

__device__ __forceinline__ void group_barrier(int gid, unsigned target) {
    __syncthreads();
    if (threadIdx.x == 0) {
        __threadfence();
        unsigned arrived = atomicAdd(&g_barg[gid][0], 1u);
        if (arrived == GRP_CTAS - 1) {
            atomicExch(&g_barg[gid][0], 0u);
            __threadfence();
            atomicAdd(&g_barg[gid][1], 1u);
        } else {
            unsigned gg;
            do {
                asm volatile("ld.acquire.gpu.u32 %0, [%1];"
                             : "=r"(gg) : "l"(&g_barg[gid][1]) : "memory");
            } while ((int)(gg - target) < 0);
        }
        __threadfence();
    }
    __syncthreads();
}

__global__ __launch_bounds__(256)
void rnn_persist(const __half* __restrict__ Whh,
                 const float* __restrict__ b_hh,
                 const __half* __restrict__ xproj) {
    extern __shared__ __align__(16) __half hsm[];
    const uint32_t WB = (uint32_t)__cvta_generic_to_shared(hsm);
    const uint32_t AB = WB + (uint32_t)RNN_W_BYTES;
    const int tid = threadIdx.x, lane = tid & 31, wid = tid >> 5;
    const int bm = blockIdx.y * BM, bn = blockIdx.x * BN;
    const int gid = blockIdx.y;
    const int warp_m = wid >> 1, warp_n = wid & 1;   // 4 x 2
    const int wm = warp_m * 32, wn = warp_n * 32;
    constexpr int CH = HH / BK;                       // 32

    unsigned gen0 = 0;
    if (tid == 0)
        asm volatile("ld.acquire.gpu.u32 %0, [%1];"
                     : "=r"(gen0) : "l"(&g_barg[gid][1]) : "memory");

    // one-time: load W tile [BN x HH] into 8x8-tiled smem (8192 16B pieces)
    for (int q = tid; q < BN * (HH / 8); q += 256) {
        const int n = q >> 7;
        const int kb = q & 127;
        const uint32_t dst = WB + (uint32_t)((((n >> 3) * 128 + kb) * 128) + (n & 7) * 16);
        cp16(dst, Whh + (size_t)(bn + n) * HH + kb * 8);
    }
    CP_COMMIT();

    auto load_A = [&](const __half* h, int k0, int s) {
        #pragma unroll
        for (int i = 0; i < 2; i++) {
            const int p = tid + i * 256;
            const int row = p >> 2, kb = p & 3;
            const uint32_t dst = AB + (uint32_t)(s * RNN_A_STAGE)
                + (uint32_t)(((((row >> 3) << 2) + kb) * 128) + (row & 7) * 16);
            cp16(dst, h + (size_t)(bm + row) * HH + k0 + kb * 8);
        }
    };

    const int g = lane >> 3, lr = lane & 7;
    const uint32_t aoff_lane = (uint32_t)((g & 1) * 512 + (g >> 1) * 128 + lr * 16);
    const uint32_t boff_lane = (uint32_t)((g >> 1) * 16384 + (g & 1) * 128 + lr * 16);
    const uint32_t a_mb_base = (uint32_t)(warp_m * 4) * 512;
    const uint32_t b_nb_base = (uint32_t)(warp_n * 4) * 16384;

    const int crow = lane >> 2, ccol = (lane & 3) * 2;

    // ---- step 0 (h0 = 0): h1 = tanh(b_hh + x0); no GEMM, overlaps W load ----
    {
        __half* Nxt = g_h[1];
        const __half* xrow = xproj;   // t = 0
        #pragma unroll
        for (int i = 0; i < 2; i++)
            #pragma unroll
            for (int j = 0; j < 4; j++)
                #pragma unroll
                for (int half = 0; half < 2; half++) {
                    const int m = bm + wm + i * 16 + crow + half * 8;
                    const int n = bn + wn + j * 8 + ccol;
                    __half2 av = *reinterpret_cast<const __half2*>(&xrow[(size_t)m * HH + n]);
                    float v0 = fast_tanh(b_hh[n]     + __half2float(av.x));
                    float v1 = fast_tanh(b_hh[n + 1] + __half2float(av.y));
                    __half2 hp = { __float2half_rn(v0), __float2half_rn(v1) };
                    *reinterpret_cast<__half2*>(&Nxt[(size_t)m * HH + n]) = hp;
                }
    }
    CP_WAIT(0);            // W tile resident
    group_barrier(gid, gen0 + 1);

    for (int t = 1; t < TT; t++) {
        const int cur = t & 1;
        const __half* Acur = g_h[cur];
        __half* Nxt = g_h[cur ^ 1];
        const __half* xrow = xproj + (size_t)t * BB * HH;

        float acc[2][4][4] = {};

        #pragma unroll
        for (int s = 0; s < STAGES - 1; s++) { load_A(Acur, s * BK, s); CP_COMMIT(); }

        for (int c = 0; c < CH; c++) {
            CP_WAIT(STAGES - 2);
            __syncthreads();
            const int pc = c + STAGES - 1;
            if (pc < CH) load_A(Acur, pc * BK, pc % STAGES);
            CP_COMMIT();

            const uint32_t stA = AB + (uint32_t)((c % STAGES) * RNN_A_STAGE);
            const uint32_t kbW = (uint32_t)(c * 4) * 128;
            #pragma unroll
            for (int kk = 0; kk < 2; kk++) {
                uint32_t a4[2][4], b4[2][4];
                #pragma unroll
                for (int i = 0; i < 2; i++)
                    ldsm_x4(a4[i], stA + a_mb_base + (uint32_t)(i * 2) * 512
                                   + (uint32_t)(kk * 2) * 128 + aoff_lane);
                #pragma unroll
                for (int u = 0; u < 2; u++)
                    ldsm_x4(b4[u], WB + b_nb_base + (uint32_t)(u * 2) * 16384
                                   + kbW + (uint32_t)(kk * 2) * 128 + boff_lane);
                #pragma unroll
                for (int i = 0; i < 2; i++)
                    #pragma unroll
                    for (int j = 0; j < 4; j++)
                        mma_f16(acc[i][j], a4[i], &b4[j >> 1][(j & 1) * 2]);
            }
        }

        // epilogue: h_next = fast_tanh(acc + b_hh + xproj[t]) -> single fp16
        #pragma unroll
        for (int i = 0; i < 2; i++)
            #pragma unroll
            for (int j = 0; j < 4; j++)
                #pragma unroll
                for (int half = 0; half < 2; half++) {
                    const int m = bm + wm + i * 16 + crow + half * 8;
                    const int n = bn + wn + j * 8 + ccol;
                    __half2 av = *reinterpret_cast<const __half2*>(&xrow[(size_t)m * HH + n]);
                    float v0 = fast_tanh(acc[i][j][half * 2 + 0] + b_hh[n]     + __half2float(av.x));
                    float v1 = fast_tanh(acc[i][j][half * 2 + 1] + b_hh[n + 1] + __half2float(av.y));
                    __half2 hp = { __float2half_rn(v0), __float2half_rn(v1) };
                    *reinterpret_cast<__half2*>(&Nxt[(size_t)m * HH + n]) = hp;
                }

        if (t + 1 < TT) group_barrier(gid, gen0 + (unsigned)(t + 1));
    }
}

// ---------------------------------------------------------------------------
// fused weight prep (R11): [0,512) transpose-split W_emb; [512,1024) split
// W_ih; [1024,2048) cvt W_hh; [2048,3072) cvt W_out
// ---------------------------------------------------------------------------
__global__ __launch_bounds__(256)
void wprep_kernel(const float* __restrict__ W_emb,
                  const float* __restrict__ W_ih,
                  const float* __restrict__ W_hh,
                  const float* __restrict__ W_out,
                  __nv_bfloat16* __restrict__ wembT_hi,
                  __nv_bfloat16* __restrict__ wembT_lo,
                  __nv_bfloat16* __restrict__ wih_hi,
                  __nv_bfloat16* __restrict__ wih_lo,
                  __half* __restrict__ whh,
                  __half* __restrict__ wout) {
    const int b = blockIdx.x;
    const int tid = threadIdx.x;
    if (b < 512) {
        __shared__ float t[32][33];
        const int v0 = (b & 31) * 32, e0 = (b >> 5) * 32;
        const int tx = tid & 31, ty = tid >> 5;
        for (int i = ty; i < 32; i += 8)
            t[i][tx] = W_emb[(size_t)(e0 + i) * VV + v0 + tx];
        __syncthreads();
        for (int i = ty; i < 32; i += 8) {
            float x = t[tx][i];
            __nv_bfloat16 h, l;
            bf16_split(x, h, l);
            size_t o = (size_t)(v0 + i) * EE + e0 + tx;
            wembT_hi[o] = h;
            wembT_lo[o] = l;
        }
    } else if (b < 1024) {
        const int idx = (b - 512) * 256 + tid;
        float4 v = reinterpret_cast<const float4*>(W_ih)[idx];
        __nv_bfloat162 hp0, hp1, lp0, lp1;
        bf16_split(v.x, hp0.x, lp0.x);
        bf16_split(v.y, hp0.y, lp0.y);
        bf16_split(v.z, hp1.x, lp1.x);
        bf16_split(v.w, hp1.y, lp1.y);
        reinterpret_cast<__nv_bfloat162*>(wih_hi)[idx * 2 + 0] = hp0;
        reinterpret_cast<__nv_bfloat162*>(wih_hi)[idx * 2 + 1] = hp1;
        reinterpret_cast<__nv_bfloat162*>(wih_lo)[idx * 2 + 0] = lp0;
        reinterpret_cast<__nv_bfloat162*>(wih_lo)[idx * 2 + 1] = lp1;
    } else {
        const bool is_hh = b < 2048;
        const int idx = (b - (is_hh ? 1024 : 2048)) * 256 + tid;
        const float* src = is_hh ? W_hh : W_out;
        __half* dst = is_hh ? whh : wout;
        float4 v = reinterpret_cast<const float4*>(src)[idx];
        __half2 p0 = { __float2half_rn(v.x), __float2half_rn(v.y) };
        __half2 p1 = { __float2half_rn(v.z), __float2half_rn(v.w) };
        reinterpret_cast<__half2*>(dst)[idx * 2 + 0] = p0;
        reinterpret_cast<__half2*>(dst)[idx * 2 + 1] = p1;
    }
}

// bf[h] = sum_e W_ih[h,e] * b_emb[e] + b_ih[h]
__global__ void bfused_kernel(const float* __restrict__ W_ih,
                              const float* __restrict__ b_emb,
                              const float* __restrict__ b_ih,
                              float* __restrict__ out) {
    int h = blockIdx.x * blockDim.x + threadIdx.x;
    if (h >= HH) return;
    float s = b_ih[h];
    const float* row = W_ih + (size_t)h * EE;
    #pragma unroll 4
    for (int e = 0; e < EE; e++) s += row[e] * b_emb[e];
    out[h] = s;
}

__global__ void cvt_f16_kernel(const float* __restrict__ in,
                               __half* __restrict__ out, int n4) {
    int idx = blockIdx.x * blockDim.x + threadIdx.x;
    for (; idx < n4; idx += gridDim.x * blockDim.x) {
        float4 v = reinterpret_cast<const float4*>(in)[idx];
        __half2 p0 = { __float2half_rn(v.x), __float2half_rn(v.y) };
        __half2 p1 = { __float2half_rn(v.z), __float2half_rn(v.w) };
        reinterpret_cast<__half2*>(out)[idx * 2 + 0] = p0;
        reinterpret_cast<__half2*>(out)[idx * 2 + 1] = p1;
    }
}

// ---------------------------------------------------------------------------
extern "C" void kernel_launch(void* const* d_in, const int* in_sizes, int n_in,
                              void* d_out, int out_size) {
    const float* msg   = (const float*)d_in[0];
    const float* W_emb = (const float*)d_in[1];
    const float* b_emb = (const float*)d_in[2];
    const float* W_ih  = (const float*)d_in[3];
    const float* b_ih  = (const float*)d_in[4];
    const float* W_hh  = (const float*)d_in[5];
    const float* b_hh  = (const float*)d_in[6];
    const float* W_out = (const float*)d_in[7];
    const float* b_out = (const float*)d_in[8];
    float* out = (float*)d_out;

    float* bfused;
    __half *xproj, *msg_h, *wf, *whh, *wout, *hbuf;
    __nv_bfloat16 *wembT_hi, *wembT_lo, *wih_hi, *wih_lo;
    cudaGetSymbolAddress((void**)&bfused,   g_bfused);
    cudaGetSymbolAddress((void**)&xproj,    g_xproj);
    cudaGetSymbolAddress((void**)&msg_h,    g_msg_h);
    cudaGetSymbolAddress((void**)&wembT_hi, g_wembT_hi);
    cudaGetSymbolAddress((void**)&wembT_lo, g_wembT_lo);
    cudaGetSymbolAddress((void**)&wih_hi,   g_wih_hi);
    cudaGetSymbolAddress((void**)&wih_lo,   g_wih_lo);
    cudaGetSymbolAddress((void**)&wf,       g_wf);
    cudaGetSymbolAddress((void**)&whh,      g_whh);
    cudaGetSymbolAddress((void**)&wout,     g_wout);
    cudaGetSymbolAddress((void**)&hbuf,     g_h);

    constexpr int H1_SMEM = STAGES * (A_ELE + B_ELE) * 2;   // 46080
    cudaFuncSetAttribute(mma_gemm_bf3, cudaFuncAttributeMaxDynamicSharedMemorySize, BF3_SMEM);
    cudaFuncSetAttribute(mma_gemm_h<1>, cudaFuncAttributeMaxDynamicSharedMemorySize, H1_SMEM);
    cudaFuncSetAttribute(mma_gemm_h<0>, cudaFuncAttributeMaxDynamicSharedMemorySize, H1_SMEM);
    cudaFuncSetAttribute(rnn_persist, cudaFuncAttributeMaxDynamicSharedMemorySize, RNN_SMEM);

    // launch #1: all weight preps fused
    wprep_kernel<<<3072, 256>>>(W_emb, W_ih, W_hh, W_out,
                                wembT_hi, wembT_lo, wih_hi, wih_lo, whh, wout);
    // launch #2
    bfused_kernel<<<(HH + 255) / 256, 256>>>(W_ih, b_emb, b_ih, bfused);
    // launch #3
    cvt_f16_kernel<<<8192, 256>>>(msg, msg_h, BB * TT * VV / 4);

    // launch #4: W_fused = W_ih @ W_emb  (bf16 3-term, fp16 out)
    mma_gemm_bf3<<<dim3(VV / BN, HH / BM), 256, BF3_SMEM>>>(
        wih_hi, wih_lo, wembT_hi, wembT_lo, wf, HH, VV, EE);

    // launch #5: x_proj = msg @ W_fused^T + b_fused -> fp16, scatter
    mma_gemm_h<1><<<dim3(HH / BN, (BB * TT) / BM), 256, H1_SMEM>>>(
        msg_h, wf, bfused, nullptr, xproj, BB * TT, HH, VV);

    // launch #6: persistent recurrence (exact R11 config + fast_tanh)
    rnn_persist<<<dim3(HH / BN, BB / BM), 256, RNN_SMEM>>>(whh, b_hh, xproj);

    // launch #7: out = h_T @ W_out^T + b_out
    mma_gemm_h<0><<<dim3(OO / BN, BB / BM), 256, H1_SMEM>>>(
        hbuf, wout, b_out, out, nullptr, BB, OO, HH);
}

// round 17
// speedup vs baseline: 1.1495x; 1.0414x over previous
#include <cuda_runtime.h>
#include <cuda_bf16.h>
#include <cuda_fp16.h>
#include <cstddef>
#include <cstdint>

#define BB   1024
#define TT   32
#define VV   1024
#define EE   512
#define HH   1024
#define OO   1024

// ---------------- device scratch (no runtime allocation) -------------------
__device__ float g_bfused[HH];
__device__ __half g_xproj[TT * BB * HH];     // fp16, bias folded in
__device__ __half g_msg_h[BB * TT * VV];
__device__ __nv_bfloat16 g_wembT_hi[VV * EE];
__device__ __nv_bfloat16 g_wembT_lo[VV * EE];
__device__ __nv_bfloat16 g_wih_hi[HH * EE];
__device__ __nv_bfloat16 g_wih_lo[HH * EE];
__device__ __half g_wf[HH * VV];             // W_fused, single fp16
__device__ __half g_whh[HH * HH];            // W_hh, single fp16
__device__ __half g_wout[OO * HH];           // W_out, single fp16
__device__ __half g_h[2][BB * HH];           // hidden state, single fp16
// per-bm-group barriers: [gid][0]=arrive count, [gid][1]=generation
// generation is monotonic across graph replays (targets are gen0-relative)
__device__ unsigned g_barg[8][2];

// ---------------- helpers ---------------------------------------------------
__device__ __forceinline__ void bf16_split(float x, __nv_bfloat16& h, __nv_bfloat16& l) {
    h = __float2bfloat16(x);
    l = __float2bfloat16(x - __bfloat162float(h));
}

// fast tanh via MUFU exp: tanh(x) = (e^{2x}-1)/(e^{2x}+1); clamp avoids inf/inf
__device__ __forceinline__ float fast_tanh(float x) {
    x = fminf(9.0f, fmaxf(-9.0f, x));
    float e = __expf(2.0f * x);
    return __fdividef(e - 1.0f, e + 1.0f);
}

__device__ __forceinline__ void ldsm_x4(uint32_t* r, uint32_t addr) {
    asm volatile("ldmatrix.sync.aligned.m8n8.x4.shared.b16 {%0,%1,%2,%3}, [%4];"
                 : "=r"(r[0]), "=r"(r[1]), "=r"(r[2]), "=r"(r[3]) : "r"(addr));
}

__device__ __forceinline__ void mma_bf16(float* d, const uint32_t* a, const uint32_t* b) {
    asm volatile("mma.sync.aligned.m16n8k16.row.col.f32.bf16.bf16.f32 "
                 "{%0,%1,%2,%3}, {%4,%5,%6,%7}, {%8,%9}, {%0,%1,%2,%3};"
                 : "+f"(d[0]), "+f"(d[1]), "+f"(d[2]), "+f"(d[3])
                 : "r"(a[0]), "r"(a[1]), "r"(a[2]), "r"(a[3]),
                   "r"(b[0]), "r"(b[1]));
}

__device__ __forceinline__ void mma_f16(float* d, const uint32_t* a, const uint32_t* b) {
    asm volatile("mma.sync.aligned.m16n8k16.row.col.f32.f16.f16.f32 "
                 "{%0,%1,%2,%3}, {%4,%5,%6,%7}, {%8,%9}, {%0,%1,%2,%3};"
                 : "+f"(d[0]), "+f"(d[1]), "+f"(d[2]), "+f"(d[3])
                 : "r"(a[0]), "r"(a[1]), "r"(a[2]), "r"(a[3]),
                   "r"(b[0]), "r"(b[1]));
}

__device__ __forceinline__ void cp16(uint32_t dst, const void* src) {
    asm volatile("cp.async.cg.shared.global [%0], [%1], 16;" :: "r"(dst), "l"(src));
}
#define CP_COMMIT() asm volatile("cp.async.commit_group;" ::: "memory")
#define CP_WAIT(n)  asm volatile("cp.async.wait_group %0;" :: "n"(n) : "memory")

// ---------------- tiling constants ------------------------------------------
constexpr int BM = 128, BN = 64, BK = 32, LDT = BK + 8, STAGES = 3;
constexpr int A_ELE = BM * LDT;                 // 5120
constexpr int B_ELE = BN * LDT;                 // 2560
constexpr int BF3_STG = 2 * A_ELE + 2 * B_ELE;
constexpr int BF3_SMEM = STAGES * BF3_STG * 2;
#define OFF_AHI 0
#define OFF_ALO (A_ELE)
#define OFF_BHI (2 * A_ELE)
#define OFF_BLO (2 * A_ELE + B_ELE)

// ---------------------------------------------------------------------------
// bf16 3-term GEMM (only for W_fused = W_ih @ W_emb, output single fp16)
// ---------------------------------------------------------------------------
__global__ __launch_bounds__(256)
void mma_gemm_bf3(const __nv_bfloat16* __restrict__ Ahi,
                  const __nv_bfloat16* __restrict__ Alo,
                  const __nv_bfloat16* __restrict__ Bhi,
                  const __nv_bfloat16* __restrict__ Blo,
                  __half* __restrict__ Cout,
                  int M, int N, int K) {
    extern __shared__ __align__(16) __nv_bfloat16 smem[];
    const uint32_t sb = (uint32_t)__cvta_generic_to_shared(smem);
    const int tid = threadIdx.x, lane = tid & 31, wid = tid >> 5;
    const int bm = blockIdx.y * BM, bn = blockIdx.x * BN;
    const int wm = (wid >> 2) * 64, wn = (wid & 3) * 16;
    const int CH = K / BK;

    const int a_r0 = tid >> 2, a_c = (tid & 3) * 8;
    const int a_r1 = (tid + 256) >> 2;
    const int b_r = tid >> 2;

    auto load_chunk = [&](int k0, int s) {
        const uint32_t st = sb + (uint32_t)(s * BF3_STG) * 2;
        const size_t ga0 = (size_t)(bm + a_r0) * K + k0 + a_c;
        const size_t ga1 = (size_t)(bm + a_r1) * K + k0 + a_c;
        const size_t gb  = (size_t)(bn + b_r ) * K + k0 + a_c;
        const uint32_t d0 = (uint32_t)(a_r0 * LDT + a_c) * 2;
        const uint32_t d1 = (uint32_t)(a_r1 * LDT + a_c) * 2;
        const uint32_t db = (uint32_t)(b_r  * LDT + a_c) * 2;
        cp16(st + OFF_AHI * 2 + d0, Ahi + ga0);
        cp16(st + OFF_AHI * 2 + d1, Ahi + ga1);
        cp16(st + OFF_ALO * 2 + d0, Alo + ga0);
        cp16(st + OFF_ALO * 2 + d1, Alo + ga1);
        cp16(st + OFF_BHI * 2 + db, Bhi + gb);
        cp16(st + OFF_BLO * 2 + db, Blo + gb);
    };

    const int a_row = wm + (lane & 7) + ((lane >> 3) & 1) * 8;
    const int a_col = (lane >> 4) * 8;
    const int b_row = wn + (lane >> 4) * 8 + (lane & 7);
    const int b_col = ((lane >> 3) & 1) * 8;
    const uint32_t aoff = (uint32_t)(a_row * LDT + a_col) * 2;
    const uint32_t boff = (uint32_t)(b_row * LDT + b_col) * 2;

    float acc[4][2][4] = {};

    #pragma unroll
    for (int s = 0; s < STAGES - 1; s++) { load_chunk(s * BK, s); CP_COMMIT(); }

    for (int c = 0; c < CH; c++) {
        CP_WAIT(STAGES - 2);
        __syncthreads();
        const int pc = c + STAGES - 1;
        if (pc < CH) load_chunk(pc * BK, pc % STAGES);
        CP_COMMIT();

        const uint32_t st = sb + (uint32_t)((c % STAGES) * BF3_STG) * 2;
        #pragma unroll
        for (int kk = 0; kk < BK; kk += 16) {
            uint32_t ah[4][4], al[4][4], bh[4], bl[4];
            #pragma unroll
            for (int i = 0; i < 4; i++) {
                ldsm_x4(ah[i], st + OFF_AHI * 2 + aoff + (uint32_t)(i * 16 * LDT + kk) * 2);
                ldsm_x4(al[i], st + OFF_ALO * 2 + aoff + (uint32_t)(i * 16 * LDT + kk) * 2);
            }
            ldsm_x4(bh, st + OFF_BHI * 2 + boff + (uint32_t)kk * 2);
            ldsm_x4(bl, st + OFF_BLO * 2 + boff + (uint32_t)kk * 2);
            #pragma unroll
            for (int i = 0; i < 4; i++)
                #pragma unroll
                for (int j = 0; j < 2; j++) {
                    mma_bf16(acc[i][j], ah[i], &bh[j * 2]);
                    mma_bf16(acc[i][j], ah[i], &bl[j * 2]);
                    mma_bf16(acc[i][j], al[i], &bh[j * 2]);
                }
        }
    }

    const int crow = lane >> 2, ccol = (lane & 3) * 2;
    #pragma unroll
    for (int i = 0; i < 4; i++)
        #pragma unroll
        for (int j = 0; j < 2; j++)
            #pragma unroll
            for (int half = 0; half < 2; half++) {
                const int m = bm + wm + i * 16 + crow + half * 8;
                const int n = bn + wn + j * 8 + ccol;
                __half2 hp = { __float2half_rn(acc[i][j][half * 2 + 0]),
                               __float2half_rn(acc[i][j][half * 2 + 1]) };
                *reinterpret_cast<__half2*>(&Cout[(size_t)m * N + n]) = hp;
            }
}

// ---------------------------------------------------------------------------
// fp16 GEMM (padded layout), 1 B plane:
//   OUT 0: fp32 out, no scatter          (out = h @ W_out^T + b_out)
//   OUT 1: fp16 out, scatter m -> (m%TT)*BB + m/TT   (x_proj)
// ---------------------------------------------------------------------------
template <int OUT>
__global__ __launch_bounds__(256)
void mma_gemm_h(const __half* __restrict__ A,
                const __half* __restrict__ Bhi,
                const float* __restrict__ bias,
                float* __restrict__ Cf,
                __half* __restrict__ Ch,
                int M, int N, int K) {
    constexpr int STG = A_ELE + B_ELE;
    extern __shared__ __align__(16) __half hsmem[];
    const uint32_t sb = (uint32_t)__cvta_generic_to_shared(hsmem);
    const int tid = threadIdx.x, lane = tid & 31, wid = tid >> 5;
    const int bm = blockIdx.y * BM, bn = blockIdx.x * BN;
    const int wm = (wid >> 2) * 64, wn = (wid & 3) * 16;
    const int CH = K / BK;

    const int a_r0 = tid >> 2, a_c = (tid & 3) * 8;
    const int a_r1 = (tid + 256) >> 2;
    const int b_r = tid >> 2;

    auto load_chunk = [&](int k0, int s) {
        const uint32_t st = sb + (uint32_t)(s * STG) * 2;
        const size_t ga0 = (size_t)(bm + a_r0) * K + k0 + a_c;
        const size_t ga1 = (size_t)(bm + a_r1) * K + k0 + a_c;
        const size_t gb  = (size_t)(bn + b_r ) * K + k0 + a_c;
        const uint32_t d0 = (uint32_t)(a_r0 * LDT + a_c) * 2;
        const uint32_t d1 = (uint32_t)(a_r1 * LDT + a_c) * 2;
        const uint32_t db = (uint32_t)(b_r  * LDT + a_c) * 2;
        cp16(st + d0, A + ga0);
        cp16(st + d1, A + ga1);
        cp16(st + (uint32_t)A_ELE * 2 + db, Bhi + gb);
    };

    const int a_row = wm + (lane & 7) + ((lane >> 3) & 1) * 8;
    const int a_col = (lane >> 4) * 8;
    const int b_row = wn + (lane >> 4) * 8 + (lane & 7);
    const int b_col = ((lane >> 3) & 1) * 8;
    const uint32_t aoff = (uint32_t)(a_row * LDT + a_col) * 2;
    const uint32_t boff = (uint32_t)(b_row * LDT + b_col) * 2;

    float acc[4][2][4] = {};

    #pragma unroll
    for (int s = 0; s < STAGES - 1; s++) { load_chunk(s * BK, s); CP_COMMIT(); }

    for (int c = 0; c < CH; c++) {
        CP_WAIT(STAGES - 2);
        __syncthreads();
        const int pc = c + STAGES - 1;
        if (pc < CH) load_chunk(pc * BK, pc % STAGES);
        CP_COMMIT();

        const uint32_t st = sb + (uint32_t)((c % STAGES) * STG) * 2;
        #pragma unroll
        for (int kk = 0; kk < BK; kk += 16) {
            uint32_t a4[4][4], bh[4];
            #pragma unroll
            for (int i = 0; i < 4; i++)
                ldsm_x4(a4[i], st + aoff + (uint32_t)(i * 16 * LDT + kk) * 2);
            ldsm_x4(bh, st + (uint32_t)A_ELE * 2 + boff + (uint32_t)kk * 2);
            #pragma unroll
            for (int i = 0; i < 4; i++)
                #pragma unroll
                for (int j = 0; j < 2; j++)
                    mma_f16(acc[i][j], a4[i], &bh[j * 2]);
        }
    }

    const int crow = lane >> 2, ccol = (lane & 3) * 2;
    #pragma unroll
    for (int i = 0; i < 4; i++)
        #pragma unroll
        for (int j = 0; j < 2; j++)
            #pragma unroll
            for (int half = 0; half < 2; half++) {
                const int m = bm + wm + i * 16 + crow + half * 8;
                const int n = bn + wn + j * 8 + ccol;
                float v0 = acc[i][j][half * 2 + 0] + bias[n];
                float v1 = acc[i][j][half * 2 + 1] + bias[n + 1];
                if (OUT == 0) {
                    float2 r = { v0, v1 };
                    *reinterpret_cast<float2*>(&Cf[(size_t)m * N + n]) = r;
                } else {
                    const size_t om = (size_t)(m % TT) * BB + (size_t)(m / TT);
                    __half2 hp = { __float2half_rn(v0), __float2half_rn(v1) };
                    *reinterpret_cast<__half2*>(&Ch[om * N + n]) = hp;
                }
            }
}

// ---------------------------------------------------------------------------
// persistent RNN recurrence (R16 champion config): W_hh single fp16
// SMEM-RESIDENT; per-bm-group barriers; t=0 GEMM skipped; 256 threads,
// 4x2 warps, 32x32 warp tiles, BK=32, 3-stage A pipeline; fast_tanh.
// ROUND-17 CHANGE (only): stage xproj[t] epilogue tile into smem via
// cp.async (issued with stage-0 A loads), + b_hh hoisted into registers.
// smem: W 128K + 3 x 8K A + 18K xrow = 170 KB (1 CTA/SM).
// ---------------------------------------------------------------------------
constexpr unsigned GRP_CTAS = HH / BN;              // 16
constexpr int RNN_W_BYTES = BN * HH * 2;            // 131072
constexpr int RNN_A_STAGE = BM * BK * 2;            // 8192
constexpr int XR_STRIDE = 144;                      // padded row stride (bytes)
constexpr int XR_BYTES  = BM * XR_STRIDE;           // 18432
constexpr int RNN_SMEM = RNN_W_BYTES + STAGES * RNN_A_STAGE + XR_BYTES; // 174080

__device__ __forceinline__ void group_barrier(int gid, unsigned target) {
    __syncthreads();
    if (threadIdx.x == 0) {
        __threadfence();
        unsigned arrived = atomicAdd(&g_barg[gid][0], 1u);
        if (arrived == GRP_CTAS - 1) {
            atomicExch(&g_barg[gid][0], 0u);
            __threadfence();
            atomicAdd(&g_barg[gid][1], 1u);
        } else {
            unsigned gg;
            do {
                asm volatile("ld.acquire.gpu.u32 %0, [%1];"
                             : "=r"(gg) : "l"(&g_barg[gid][1]) : "memory");
            } while ((int)(gg - target) < 0);
        }
        __threadfence();
    }
    __syncthreads();
}

__global__ __launch_bounds__(256)
void rnn_persist(const __half* __restrict__ Whh,
                 const float* __restrict__ b_hh,
                 const __half* __restrict__ xproj) {
    extern __shared__ __align__(16) __half hsm[];
    const uint32_t WB = (uint32_t)__cvta_generic_to_shared(hsm);
    const uint32_t AB = WB + (uint32_t)RNN_W_BYTES;
    const uint32_t XB = AB + (uint32_t)(STAGES * RNN_A_STAGE);
    __half* xsm = hsm + (RNN_W_BYTES + STAGES * RNN_A_STAGE) / 2;  // same region
    const int tid = threadIdx.x, lane = tid & 31, wid = tid >> 5;
    const int bm = blockIdx.y * BM, bn = blockIdx.x * BN;
    const int gid = blockIdx.y;
    const int warp_m = wid >> 1, warp_n = wid & 1;   // 4 x 2
    const int wm = warp_m * 32, wn = warp_n * 32;
    constexpr int CH = HH / BK;                       // 32

    unsigned gen0 = 0;
    if (tid == 0)
        asm volatile("ld.acquire.gpu.u32 %0, [%1];"
                     : "=r"(gen0) : "l"(&g_barg[gid][1]) : "memory");

    // one-time: load W tile [BN x HH] into 8x8-tiled smem (8192 16B pieces)
    for (int q = tid; q < BN * (HH / 8); q += 256) {
        const int n = q >> 7;
        const int kb = q & 127;
        const uint32_t dst = WB + (uint32_t)((((n >> 3) * 128 + kb) * 128) + (n & 7) * 16);
        cp16(dst, Whh + (size_t)(bn + n) * HH + kb * 8);
    }
    CP_COMMIT();

    auto load_A = [&](const __half* h, int k0, int s) {
        #pragma unroll
        for (int i = 0; i < 2; i++) {
            const int p = tid + i * 256;
            const int row = p >> 2, kb = p & 3;
            const uint32_t dst = AB + (uint32_t)(s * RNN_A_STAGE)
                + (uint32_t)(((((row >> 3) << 2) + kb) * 128) + (row & 7) * 16);
            cp16(dst, h + (size_t)(bm + row) * HH + k0 + kb * 8);
        }
    };

    // stage xproj[t] epilogue tile [128 x 64] into padded smem (1024 pieces)
    auto load_X = [&](const __half* xrow) {
        #pragma unroll
        for (int i = 0; i < 4; i++) {
            const int p = tid + i * 256;
            const int row = p >> 3, cp = p & 7;        // 8 x 16B per row
            cp16(XB + (uint32_t)(row * XR_STRIDE + cp * 16),
                 xrow + (size_t)(bm + row) * HH + bn + cp * 8);
        }
    };

    const int g = lane >> 3, lr = lane & 7;
    const uint32_t aoff_lane = (uint32_t)((g & 1) * 512 + (g >> 1) * 128 + lr * 16);
    const uint32_t boff_lane = (uint32_t)((g >> 1) * 16384 + (g & 1) * 128 + lr * 16);
    const uint32_t a_mb_base = (uint32_t)(warp_m * 4) * 512;
    const uint32_t b_nb_base = (uint32_t)(warp_n * 4) * 16384;

    const int crow = lane >> 2, ccol = (lane & 3) * 2;

    // hoist b_hh for this thread's 4 n positions (fixed all steps)
    float2 bb[4];
    #pragma unroll
    for (int j = 0; j < 4; j++)
        bb[j] = *reinterpret_cast<const float2*>(&b_hh[bn + wn + j * 8 + ccol]);

    // ---- step 0 (h0 = 0): h1 = tanh(b_hh + x0); no GEMM, overlaps W load ----
    {
        __half* Nxt = g_h[1];
        const __half* xrow = xproj;   // t = 0
        #pragma unroll
        for (int i = 0; i < 2; i++)
            #pragma unroll
            for (int j = 0; j < 4; j++)
                #pragma unroll
                for (int half = 0; half < 2; half++) {
                    const int m = bm + wm + i * 16 + crow + half * 8;
                    const int n = bn + wn + j * 8 + ccol;
                    __half2 av = *reinterpret_cast<const __half2*>(&xrow[(size_t)m * HH + n]);
                    float v0 = fast_tanh(bb[j].x + __half2float(av.x));
                    float v1 = fast_tanh(bb[j].y + __half2float(av.y));
                    __half2 hp = { __float2half_rn(v0), __float2half_rn(v1) };
                    *reinterpret_cast<__half2*>(&Nxt[(size_t)m * HH + n]) = hp;
                }
    }
    CP_WAIT(0);            // W tile resident
    group_barrier(gid, gen0 + 1);

    for (int t = 1; t < TT; t++) {
        const int cur = t & 1;
        const __half* Acur = g_h[cur];
        __half* Nxt = g_h[cur ^ 1];
        const __half* xrow = xproj + (size_t)t * BB * HH;

        float acc[2][4][4] = {};

        // stage-0 A loads + xrow tile share one commit group
        load_A(Acur, 0, 0);
        load_X(xrow);
        CP_COMMIT();
        load_A(Acur, BK, 1);
        CP_COMMIT();

        for (int c = 0; c < CH; c++) {
            CP_WAIT(STAGES - 2);
            __syncthreads();
            const int pc = c + STAGES - 1;
            if (pc < CH) load_A(Acur, pc * BK, pc % STAGES);
            CP_COMMIT();

            const uint32_t stA = AB + (uint32_t)((c % STAGES) * RNN_A_STAGE);
            const uint32_t kbW = (uint32_t)(c * 4) * 128;
            #pragma unroll
            for (int kk = 0; kk < 2; kk++) {
                uint32_t a4[2][4], b4[2][4];
                #pragma unroll
                for (int i = 0; i < 2; i++)
                    ldsm_x4(a4[i], stA + a_mb_base + (uint32_t)(i * 2) * 512
                                   + (uint32_t)(kk * 2) * 128 + aoff_lane);
                #pragma unroll
                for (int u = 0; u < 2; u++)
                    ldsm_x4(b4[u], WB + b_nb_base + (uint32_t)(u * 2) * 16384
                                   + kbW + (uint32_t)(kk * 2) * 128 + boff_lane);
                #pragma unroll
                for (int i = 0; i < 2; i++)
                    #pragma unroll
                    for (int j = 0; j < 4; j++)
                        mma_f16(acc[i][j], a4[i], &b4[j >> 1][(j & 1) * 2]);
            }
        }

        // epilogue: h_next = fast_tanh(acc + b_hh + xrow) ; xrow from SMEM
        #pragma unroll
        for (int i = 0; i < 2; i++)
            #pragma unroll
            for (int j = 0; j < 4; j++)
                #pragma unroll
                for (int half = 0; half < 2; half++) {
                    const int lm = wm + i * 16 + crow + half * 8;    // local row
                    const int ln = wn + j * 8 + ccol;                // local col
                    __half2 av = *reinterpret_cast<const __half2*>(
                        reinterpret_cast<const char*>(xsm) + lm * XR_STRIDE + ln * 2);
                    float v0 = fast_tanh(acc[i][j][half * 2 + 0] + bb[j].x + __half2float(av.x));
                    float v1 = fast_tanh(acc[i][j][half * 2 + 1] + bb[j].y + __half2float(av.y));
                    __half2 hp = { __float2half_rn(v0), __float2half_rn(v1) };
                    *reinterpret_cast<__half2*>(
                        &Nxt[(size_t)(bm + lm) * HH + bn + ln]) = hp;
                }

        if (t + 1 < TT) group_barrier(gid, gen0 + (unsigned)(t + 1));
    }
}

// ---------------------------------------------------------------------------
// fused weight prep (R11): [0,512) transpose-split W_emb; [512,1024) split
// W_ih; [1024,2048) cvt W_hh; [2048,3072) cvt W_out
// ---------------------------------------------------------------------------
__global__ __launch_bounds__(256)
void wprep_kernel(const float* __restrict__ W_emb,
                  const float* __restrict__ W_ih,
                  const float* __restrict__ W_hh,
                  const float* __restrict__ W_out,
                  __nv_bfloat16* __restrict__ wembT_hi,
                  __nv_bfloat16* __restrict__ wembT_lo,
                  __nv_bfloat16* __restrict__ wih_hi,
                  __nv_bfloat16* __restrict__ wih_lo,
                  __half* __restrict__ whh,
                  __half* __restrict__ wout) {
    const int b = blockIdx.x;
    const int tid = threadIdx.x;
    if (b < 512) {
        __shared__ float t[32][33];
        const int v0 = (b & 31) * 32, e0 = (b >> 5) * 32;
        const int tx = tid & 31, ty = tid >> 5;
        for (int i = ty; i < 32; i += 8)
            t[i][tx] = W_emb[(size_t)(e0 + i) * VV + v0 + tx];
        __syncthreads();
        for (int i = ty; i < 32; i += 8) {
            float x = t[tx][i];
            __nv_bfloat16 h, l;
            bf16_split(x, h, l);
            size_t o = (size_t)(v0 + i) * EE + e0 + tx;
            wembT_hi[o] = h;
            wembT_lo[o] = l;
        }
    } else if (b < 1024) {
        const int idx = (b - 512) * 256 + tid;
        float4 v = reinterpret_cast<const float4*>(W_ih)[idx];
        __nv_bfloat162 hp0, hp1, lp0, lp1;
        bf16_split(v.x, hp0.x, lp0.x);
        bf16_split(v.y, hp0.y, lp0.y);
        bf16_split(v.z, hp1.x, lp1.x);
        bf16_split(v.w, hp1.y, lp1.y);
        reinterpret_cast<__nv_bfloat162*>(wih_hi)[idx * 2 + 0] = hp0;
        reinterpret_cast<__nv_bfloat162*>(wih_hi)[idx * 2 + 1] = hp1;
        reinterpret_cast<__nv_bfloat162*>(wih_lo)[idx * 2 + 0] = lp0;
        reinterpret_cast<__nv_bfloat162*>(wih_lo)[idx * 2 + 1] = lp1;
    } else {
        const bool is_hh = b < 2048;
        const int idx = (b - (is_hh ? 1024 : 2048)) * 256 + tid;
        const float* src = is_hh ? W_hh : W_out;
        __half* dst = is_hh ? whh : wout;
        float4 v = reinterpret_cast<const float4*>(src)[idx];
        __half2 p0 = { __float2half_rn(v.x), __float2half_rn(v.y) };
        __half2 p1 = { __float2half_rn(v.z), __float2half_rn(v.w) };
        reinterpret_cast<__half2*>(dst)[idx * 2 + 0] = p0;
        reinterpret_cast<__half2*>(dst)[idx * 2 + 1] = p1;
    }
}

// bf[h] = sum_e W_ih[h,e] * b_emb[e] + b_ih[h]
__global__ void bfused_kernel(const float* __restrict__ W_ih,
                              const float* __restrict__ b_emb,
                              const float* __restrict__ b_ih,
                              float* __restrict__ out) {
    int h = blockIdx.x * blockDim.x + threadIdx.x;
    if (h >= HH) return;
    float s = b_ih[h];
    const float* row = W_ih + (size_t)h * EE;
    #pragma unroll 4
    for (int e = 0; e < EE; e++) s += row[e] * b_emb[e];
    out[h] = s;
}

__global__ void cvt_f16_kernel(const float* __restrict__ in,
                               __half* __restrict__ out, int n4) {
    int idx = blockIdx.x * blockDim.x + threadIdx.x;
    for (; idx < n4; idx += gridDim.x * blockDim.x) {
        float4 v = reinterpret_cast<const float4*>(in)[idx];
        __half2 p0 = { __float2half_rn(v.x), __float2half_rn(v.y) };
        __half2 p1 = { __float2half_rn(v.z), __float2half_rn(v.w) };
        reinterpret_cast<__half2*>(out)[idx * 2 + 0] = p0;
        reinterpret_cast<__half2*>(out)[idx * 2 + 1] = p1;
    }
}

// ---------------------------------------------------------------------------
extern "C" void kernel_launch(void* const* d_in, const int* in_sizes, int n_in,
                              void* d_out, int out_size) {
    const float* msg   = (const float*)d_in[0];
    const float* W_emb = (const float*)d_in[1];
    const float* b_emb = (const float*)d_in[2];
    const float* W_ih  = (const float*)d_in[3];
    const float* b_ih  = (const float*)d_in[4];
    const float* W_hh  = (const float*)d_in[5];
    const float* b_hh  = (const float*)d_in[6];
    const float* W_out = (const float*)d_in[7];
    const float* b_out = (const float*)d_in[8];
    float* out = (float*)d_out;

    float* bfused;
    __half *xproj, *msg_h, *wf, *whh, *wout, *hbuf;
    __nv_bfloat16 *wembT_hi, *wembT_lo, *wih_hi, *wih_lo;
    cudaGetSymbolAddress((void**)&bfused,   g_bfused);
    cudaGetSymbolAddress((void**)&xproj,    g_xproj);
    cudaGetSymbolAddress((void**)&msg_h,    g_msg_h);
    cudaGetSymbolAddress((void**)&wembT_hi, g_wembT_hi);
    cudaGetSymbolAddress((void**)&wembT_lo, g_wembT_lo);
    cudaGetSymbolAddress((void**)&wih_hi,   g_wih_hi);
    cudaGetSymbolAddress((void**)&wih_lo,   g_wih_lo);
    cudaGetSymbolAddress((void**)&wf,       g_wf);
    cudaGetSymbolAddress((void**)&whh,      g_whh);
    cudaGetSymbolAddress((void**)&wout,     g_wout);
    cudaGetSymbolAddress((void**)&hbuf,     g_h);

    constexpr int H1_SMEM = STAGES * (A_ELE + B_ELE) * 2;   // 46080
    cudaFuncSetAttribute(mma_gemm_bf3, cudaFuncAttributeMaxDynamicSharedMemorySize, BF3_SMEM);
    cudaFuncSetAttribute(mma_gemm_h<1>, cudaFuncAttributeMaxDynamicSharedMemorySize, H1_SMEM);
    cudaFuncSetAttribute(mma_gemm_h<0>, cudaFuncAttributeMaxDynamicSharedMemorySize, H1_SMEM);
    cudaFuncSetAttribute(rnn_persist, cudaFuncAttributeMaxDynamicSharedMemorySize, RNN_SMEM);

    // launch #1: all weight preps fused
    wprep_kernel<<<3072, 256>>>(W_emb, W_ih, W_hh, W_out,
                                wembT_hi, wembT_lo, wih_hi, wih_lo, whh, wout);
    // launch #2
    bfused_kernel<<<(HH + 255) / 256, 256>>>(W_ih, b_emb, b_ih, bfused);
    // launch #3
    cvt_f16_kernel<<<8192, 256>>>(msg, msg_h, BB * TT * VV / 4);

    // launch #4: W_fused = W_ih @ W_emb  (bf16 3-term, fp16 out)
    mma_gemm_bf3<<<dim3(VV / BN, HH / BM), 256, BF3_SMEM>>>(
        wih_hi, wih_lo, wembT_hi, wembT_lo, wf, HH, VV, EE);

    // launch #5: x_proj = msg @ W_fused^T + b_fused -> fp16, scatter
    mma_gemm_h<1><<<dim3(HH / BN, (BB * TT) / BM), 256, H1_SMEM>>>(
        msg_h, wf, bfused, nullptr, xproj, BB * TT, HH, VV);

    // launch #6: persistent recurrence (champion + smem xrow staging)
    rnn_persist<<<dim3(HH / BN, BB / BM), 256, RNN_SMEM>>>(whh, b_hh, xproj);

    // launch #7: out = h_T @ W_out^T + b_out
    mma_gemm_h<0><<<dim3(OO / BN, BB / BM), 256, H1_SMEM>>>(
        hbuf, wout, b_out, out, nullptr, BB, OO, HH);
}